// round 6
// baseline (speedup 1.0000x reference)
#include <cuda_runtime.h>
#include <math.h>

typedef unsigned long long u64;

#define S_SPLIT 32
#define KC      128

__device__ float g_qkv_part[S_SPLIT * 32 * 6144];
__device__ float g_qkv[32 * 6144];
__device__ float g_attn[32 * 4096];
__device__ float g_wo_part[S_SPLIT * 32 * 4096];
__device__ float g_po[512 * 512];      // per (b,kvh,half): unnormalized o[4][128]
__device__ float g_ms[512 * 8];        // per partial: m[4], s[4]

__device__ __forceinline__ u64 f2pack(float lo, float hi) {
    u64 r; asm("mov.b64 %0,{%1,%2};" : "=l"(r) : "f"(lo), "f"(hi)); return r;
}
__device__ __forceinline__ u64 ffma2(u64 a, u64 b, u64 c) {
    u64 d; asm("fma.rn.f32x2 %0,%1,%2,%3;" : "=l"(d) : "l"(a), "l"(b), "l"(c)); return d;
}
__device__ __forceinline__ float f2lo(u64 v) {
    float lo, hi; asm("mov.b64 {%0,%1},%2;" : "=f"(lo), "=f"(hi) : "l"(v)); return lo;
}
__device__ __forceinline__ float f2hi(u64 v) {
    float lo, hi; asm("mov.b64 {%0,%1},%2;" : "=f"(lo), "=f"(hi) : "l"(v)); return hi;
}

// ---- split-K GEMM partial (16 rows per block-z for occupancy) -------------
__global__ __launch_bounds__(128, 4)
void gemm_split(const float* __restrict__ A, const float* __restrict__ W,
                float* __restrict__ part, int N)
{
    __shared__ float2 as2[16][KC];
    const int K = 4096;
    const int k0 = blockIdx.y * KC;
    const int c0 = blockIdx.x * 512 + threadIdx.x * 4;
    const int m0 = blockIdx.z * 16;

    for (int i = threadIdx.x; i < 16 * KC; i += 128) {
        int m = i >> 7, kk = i & (KC - 1);
        float a = A[(m0 + m) * K + k0 + kk];
        as2[m][kk] = make_float2(a, a);
    }
    __syncthreads();

    u64 acc01[16], acc23[16];
#pragma unroll
    for (int m = 0; m < 16; m++) { acc01[m] = 0ull; acc23[m] = 0ull; }

    const float* Wp = W + (size_t)k0 * N + c0;
#pragma unroll 1
    for (int kk = 0; kk < KC; kk += 2) {
        u64 w01a = *(const u64*)(Wp);
        u64 w23a = *(const u64*)(Wp + 2);
        u64 w01b = *(const u64*)(Wp + N);
        u64 w23b = *(const u64*)(Wp + N + 2);
        Wp += 2 * N;
#pragma unroll
        for (int m = 0; m < 16; m++) {
            const u64* pa = (const u64*)&as2[m][kk];
            u64 a0 = pa[0], a1 = pa[1];
            acc01[m] = ffma2(a0, w01a, acc01[m]);
            acc23[m] = ffma2(a0, w23a, acc23[m]);
            acc01[m] = ffma2(a1, w01b, acc01[m]);
            acc23[m] = ffma2(a1, w23b, acc23[m]);
        }
    }

    float* op = part + ((size_t)blockIdx.y * 32 + m0) * N + c0;
#pragma unroll
    for (int m = 0; m < 16; m++) {
        *(u64*)(op + (size_t)m * N)     = acc01[m];
        *(u64*)(op + (size_t)m * N + 2) = acc23[m];
    }
}

// ---- reduce QKV partials + RoPE ------------------------------------------
__global__ void qkv_reduce_rope(const int* __restrict__ pos1d)
{
    __shared__ float cs[64], sn[64];
    const int b = blockIdx.x;
    const int tid = threadIdx.x;

    if (tid < 64) {
        float freq = (float)pow(1.0e6, -(double)tid / 64.0);
        float ang = (float)pos1d[b] * freq;
        double sd, cd; sincos((double)ang, &sd, &cd);
        cs[tid] = (float)cd; sn[tid] = (float)sd;
    }
    __syncthreads();

    for (int idx = tid; idx < 3584; idx += blockDim.x) {
        if (idx < 2560) {
            int col1, j;
            if (idx < 2048) { int h = idx >> 6; j = idx & 63; col1 = h * 128 + j; }
            else { int t = idx - 2048; int kvh = t >> 6; j = t & 63; col1 = 4096 + kvh * 128 + j; }
            int col2 = col1 + 64;
            float x1 = 0.f, x2 = 0.f;
#pragma unroll
            for (int s = 0; s < S_SPLIT; s++) {
                x1 += g_qkv_part[(s * 32 + b) * 6144 + col1];
                x2 += g_qkv_part[(s * 32 + b) * 6144 + col2];
            }
            float c = cs[j], sv = sn[j];
            g_qkv[b * 6144 + col1] = x1 * c - x2 * sv;
            g_qkv[b * 6144 + col2] = x2 * c + x1 * sv;
        } else {
            int col = 5120 + (idx - 2560);
            float x = 0.f;
#pragma unroll
            for (int s = 0; s < S_SPLIT; s++)
                x += g_qkv_part[(s * 32 + b) * 6144 + col];
            g_qkv[b * 6144 + col] = x;
        }
    }
}

__device__ __forceinline__ float4 warpRedMax4(float4 v) {
#pragma unroll
    for (int o = 16; o > 0; o >>= 1) {
        v.x = fmaxf(v.x, __shfl_xor_sync(0xffffffffu, v.x, o));
        v.y = fmaxf(v.y, __shfl_xor_sync(0xffffffffu, v.y, o));
        v.z = fmaxf(v.z, __shfl_xor_sync(0xffffffffu, v.z, o));
        v.w = fmaxf(v.w, __shfl_xor_sync(0xffffffffu, v.w, o));
    }
    return v;
}
__device__ __forceinline__ float4 warpRedSum4(float4 v) {
#pragma unroll
    for (int o = 16; o > 0; o >>= 1) {
        v.x += __shfl_xor_sync(0xffffffffu, v.x, o);
        v.y += __shfl_xor_sync(0xffffffffu, v.y, o);
        v.z += __shfl_xor_sync(0xffffffffu, v.z, o);
        v.w += __shfl_xor_sync(0xffffffffu, v.w, o);
    }
    return v;
}
__device__ float4 blockRedMax4(float4 v, float4* red) {
    v = warpRedMax4(v);
    int w = threadIdx.x >> 5, lane = threadIdx.x & 31;
    if (lane == 0) red[w] = v;
    __syncthreads();
    if (w == 0) {
        float4 t = (lane < 8) ? red[lane] : make_float4(-1e30f, -1e30f, -1e30f, -1e30f);
        t = warpRedMax4(t);
        if (lane == 0) red[0] = t;
    }
    __syncthreads();
    return red[0];
}
__device__ float4 blockRedSum4(float4 v, float4* red) {
    v = warpRedSum4(v);
    int w = threadIdx.x >> 5, lane = threadIdx.x & 31;
    if (lane == 0) red[w] = v;
    __syncthreads();
    if (w == 0) {
        float4 t = (lane < 8) ? red[lane] : make_float4(0.f, 0.f, 0.f, 0.f);
        t = warpRedSum4(t);
        if (lane == 0) red[0] = t;
    }
    __syncthreads();
    return red[0];
}

// ---- split-KV paged attention: CTA = (b, kvh, half of 2048 keys) ----------
#define HALF_L 2048
#define ATTN_SMEM ((HALF_L * 4 + 512) * 4 + 128)

__global__ __launch_bounds__(256)
void attn_part(const float* __restrict__ kc, const float* __restrict__ vc,
               const int* __restrict__ blkoff, const int* __restrict__ kvlens)
{
    extern __shared__ float sm[];
    float* sc = sm;                    // s[ll][g], 8192 floats
    float* qp = sm + HALF_L * 4;       // q[g][d]*scale, 512 floats
    float4* red = (float4*)(sm + HALF_L * 4 + 512);
    __shared__ int pblk[32];

    const int blk  = blockIdx.x;       // b*16 + kvh*2 + half
    const int b    = blk >> 4;
    const int kvh  = (blk >> 1) & 7;
    const int half = blk & 1;
    const int base = half * HALF_L;
    const int tid  = threadIdx.x;
    const int Lv   = kvlens[b];
    const int posn = Lv - 1;
    const float* qkv_b = g_qkv + b * 6144;

    for (int i = tid; i < 512; i += 256) {
        int g = i >> 7, d = i & 127;
        qp[i] = qkv_b[(kvh * 4 + g) * 128 + d] * 0.08838834764831845f;
    }
    if (tid < 32) pblk[tid] = blkoff[b * 64 + half * 32 + tid];
    __syncthreads();

    // ---- Phase 1: QK, fully coalesced (lane i-th chunk at dims (lane8+8i)*4)
    const int lane8  = tid & 7;
    const int rowoff = tid >> 3;       // 0..31

    float4 qr[4][4];
#pragma unroll
    for (int g = 0; g < 4; g++)
#pragma unroll
        for (int i = 0; i < 4; i++)
            qr[g][i] = *(const float4*)&qp[g * 128 + (lane8 + 8 * i) * 4];

    float4 mx = make_float4(-1e30f, -1e30f, -1e30f, -1e30f);
#pragma unroll 2
    for (int pass = 0; pass < 64; pass++) {
        int ll = pass * 32 + rowoff;
        int l  = base + ll;
        const float* krow;
        if (l == posn) krow = qkv_b + 4096 + kvh * 128;
        else {
            int phys = pblk[ll >> 6];
            krow = kc + (((size_t)phys * 64 + (ll & 63)) * 8 + kvh) * 128;
        }
        float4 k0 = *(const float4*)(krow + (lane8 + 0)  * 4);
        float4 k1 = *(const float4*)(krow + (lane8 + 8)  * 4);
        float4 k2 = *(const float4*)(krow + (lane8 + 16) * 4);
        float4 k3 = *(const float4*)(krow + (lane8 + 24) * 4);
        float a0 = 0.f, a1 = 0.f, a2 = 0.f, a3 = 0.f;
#define DOTG(kk, qq, acc) acc += kk.x*qq.x + kk.y*qq.y + kk.z*qq.z + kk.w*qq.w
        DOTG(k0, qr[0][0], a0); DOTG(k1, qr[0][1], a0); DOTG(k2, qr[0][2], a0); DOTG(k3, qr[0][3], a0);
        DOTG(k0, qr[1][0], a1); DOTG(k1, qr[1][1], a1); DOTG(k2, qr[1][2], a1); DOTG(k3, qr[1][3], a1);
        DOTG(k0, qr[2][0], a2); DOTG(k1, qr[2][1], a2); DOTG(k2, qr[2][2], a2); DOTG(k3, qr[2][3], a2);
        DOTG(k0, qr[3][0], a3); DOTG(k1, qr[3][1], a3); DOTG(k2, qr[3][2], a3); DOTG(k3, qr[3][3], a3);
#undef DOTG
#pragma unroll
        for (int o = 4; o > 0; o >>= 1) {
            a0 += __shfl_xor_sync(0xffffffffu, a0, o);
            a1 += __shfl_xor_sync(0xffffffffu, a1, o);
            a2 += __shfl_xor_sync(0xffffffffu, a2, o);
            a3 += __shfl_xor_sync(0xffffffffu, a3, o);
        }
        if (lane8 == 0) ((float4*)sc)[ll] = make_float4(a0, a1, a2, a3);
        if (l < Lv) {
            mx.x = fmaxf(mx.x, a0); mx.y = fmaxf(mx.y, a1);
            mx.z = fmaxf(mx.z, a2); mx.w = fmaxf(mx.w, a3);
        }
    }
    __syncthreads();
    mx = blockRedMax4(mx, red);

    // ---- Phase 2: exp + sum ----------------------------------------------
    float4 sum = make_float4(0.f, 0.f, 0.f, 0.f);
#pragma unroll 1
    for (int i = 0; i < 8; i++) {
        int ll = tid + (i << 8);
        float4 sv = ((float4*)sc)[ll];
        bool valid = (base + ll < Lv);
        sv.x = valid ? __expf(sv.x - mx.x) : 0.f;
        sv.y = valid ? __expf(sv.y - mx.y) : 0.f;
        sv.z = valid ? __expf(sv.z - mx.z) : 0.f;
        sv.w = valid ? __expf(sv.w - mx.w) : 0.f;
        sum.x += sv.x; sum.y += sv.y; sum.z += sv.z; sum.w += sv.w;
        ((float4*)sc)[ll] = sv;
    }
    __syncthreads();
    sum = blockRedSum4(sum, red);
    __syncthreads();

    // ---- Phase 3: PV (unnormalized), batched MLP=8 ------------------------
    const int d2  = tid & 63;
    const int gp  = (tid >> 6) & 1;
    const int rep = tid >> 7;
    const u64* scu = (const u64*)sc;
    u64 accA = 0ull, accB = 0ull;
    const int lbeg = rep * (HALF_L / 2);
    const int cap  = min(HALF_L, max(0, posn - base));   // cached rows only
    const int lend = min(lbeg + HALF_L / 2, cap);

    int l = lbeg;
    for (; l + 8 <= lend; l += 8) {
        float2 v[8]; u64 p[8];
#pragma unroll
        for (int j = 0; j < 8; j++) {
            int ll = l + j;
            int phys = pblk[ll >> 6];
            v[j] = *(const float2*)(vc + (((size_t)phys * 64 + (ll & 63)) * 8 + kvh) * 128 + d2 * 2);
        }
#pragma unroll
        for (int j = 0; j < 8; j++) p[j] = scu[(l + j) * 2 + gp];
#pragma unroll
        for (int j = 0; j < 8; j++) {
            accA = ffma2(f2pack(v[j].x, v[j].x), p[j], accA);
            accB = ffma2(f2pack(v[j].y, v[j].y), p[j], accB);
        }
    }
    for (; l < lend; l++) {
        int phys = pblk[l >> 6];
        float2 v2 = *(const float2*)(vc + (((size_t)phys * 64 + (l & 63)) * 8 + kvh) * 128 + d2 * 2);
        u64 p2 = scu[l * 2 + gp];
        accA = ffma2(f2pack(v2.x, v2.x), p2, accA);
        accB = ffma2(f2pack(v2.y, v2.y), p2, accB);
    }
    {   // fresh-token V row, if it lands in this thread's range
        int pl = posn - base;
        if (pl >= lbeg && pl < lbeg + HALF_L / 2) {
            float2 v2 = *(const float2*)(qkv_b + 5120 + kvh * 128 + d2 * 2);
            u64 p2 = scu[pl * 2 + gp];
            accA = ffma2(f2pack(v2.x, v2.x), p2, accA);
            accB = ffma2(f2pack(v2.y, v2.y), p2, accB);
        }
    }
    __syncthreads();
    float4* comb = (float4*)sc;
    comb[tid] = make_float4(f2lo(accA), f2hi(accA), f2lo(accB), f2hi(accB));
    __syncthreads();
    if (rep == 0) {
        float4 o = comb[tid], p = comb[tid + 128];
        o.x += p.x; o.y += p.y; o.z += p.z; o.w += p.w;
        int g0 = gp * 2, g1 = g0 + 1;
        int d0 = d2 * 2, d1 = d0 + 1;
        float* ob = g_po + blk * 512;
        ob[g0 * 128 + d0] = o.x;
        ob[g1 * 128 + d0] = o.y;
        ob[g0 * 128 + d1] = o.z;
        ob[g1 * 128 + d1] = o.w;
    }
    if (tid == 0) {
        float* msp = g_ms + blk * 8;
        msp[0] = mx.x; msp[1] = mx.y; msp[2] = mx.z; msp[3] = mx.w;
        msp[4] = sum.x; msp[5] = sum.y; msp[6] = sum.z; msp[7] = sum.w;
    }
}

// ---- combine the two KV-halves -------------------------------------------
__global__ void attn_combine()
{
    const int pair = blockIdx.x;          // b*8 + kvh
    const int b = pair >> 3, kvh = pair & 7;
    const int p0 = pair * 2, p1 = p0 + 1;
    const int tid = threadIdx.x;

    __shared__ float e0s[4], e1s[4], invs[4];
    if (tid < 4) {
        float m0 = g_ms[p0 * 8 + tid], s0 = g_ms[p0 * 8 + 4 + tid];
        float m1 = g_ms[p1 * 8 + tid], s1 = g_ms[p1 * 8 + 4 + tid];
        float M = fmaxf(m0, m1);
        float e0 = __expf(m0 - M), e1 = __expf(m1 - M);
        float s = s0 * e0 + s1 * e1;
        e0s[tid] = e0; e1s[tid] = e1; invs[tid] = 1.f / s;
    }
    __syncthreads();
#pragma unroll
    for (int j = 0; j < 2; j++) {
        int i = tid + j * 256;            // 512 outputs
        int g = i >> 7;
        float o = g_po[p0 * 512 + i] * e0s[g] + g_po[p1 * 512 + i] * e1s[g];
        g_attn[b * 4096 + kvh * 512 + i] = o * invs[g];
    }
}

// ---- final split-K reduction ----------------------------------------------
__global__ void reduce_out(float* __restrict__ out, int n)
{
    int i = blockIdx.x * blockDim.x + threadIdx.x;
    if (i < n) {
        float x = 0.f;
#pragma unroll
        for (int s = 0; s < S_SPLIT; s++) x += g_wo_part[(size_t)s * n + i];
        out[i] = x;
    }
}

extern "C" void kernel_launch(void* const* d_in, const int* in_sizes, int n_in,
                              void* d_out, int out_size)
{
    const float* hidden = (const float*)d_in[0];
    const float* wqkv   = (const float*)d_in[1];
    const float* wo     = (const float*)d_in[2];
    const float* kc     = (const float*)d_in[3];
    const float* vc     = (const float*)d_in[4];
    const int*   pos1d  = (const int*)d_in[5];
    const int*   blkoff = (const int*)d_in[6];
    const int*   kvlens = (const int*)d_in[7];
    float* out = (float*)d_out;

    static bool attr_done = false;
    if (!attr_done) {
        cudaFuncSetAttribute(attn_part, cudaFuncAttributeMaxDynamicSharedMemorySize, ATTN_SMEM);
        attr_done = true;
    }

    float *qkv_part, *wo_part, *attn_in;
    cudaGetSymbolAddress((void**)&qkv_part, g_qkv_part);
    cudaGetSymbolAddress((void**)&wo_part,  g_wo_part);
    cudaGetSymbolAddress((void**)&attn_in,  g_attn);

    gemm_split<<<dim3(12, 32, 2), 128>>>(hidden, wqkv, qkv_part, 6144);
    qkv_reduce_rope<<<32, 256>>>(pos1d);
    attn_part<<<512, 256, ATTN_SMEM>>>(kc, vc, blkoff, kvlens);
    attn_combine<<<256, 256>>>();
    gemm_split<<<dim3(8, 32, 2), 128>>>(attn_in, wo, wo_part, 4096);
    reduce_out<<<512, 256>>>(out, 32 * 4096);
}

// round 9
// speedup vs baseline: 1.7397x; 1.7397x over previous
#include <cuda_runtime.h>
#include <math.h>
#include <stdint.h>

typedef unsigned long long u64;

#define S_SPLIT 32
#define KC      128

__device__ float g_qkv_part[S_SPLIT * 32 * 6144];
__device__ float g_qkv[32 * 6144];
__device__ float g_attn[32 * 4096];
__device__ float g_wo_part[S_SPLIT * 32 * 4096];

__device__ __forceinline__ u64 f2pack(float lo, float hi) {
    u64 r; asm("mov.b64 %0,{%1,%2};" : "=l"(r) : "f"(lo), "f"(hi)); return r;
}
__device__ __forceinline__ u64 ffma2(u64 a, u64 b, u64 c) {
    u64 d; asm("fma.rn.f32x2 %0,%1,%2,%3;" : "=l"(d) : "l"(a), "l"(b), "l"(c)); return d;
}
__device__ __forceinline__ float f2lo(u64 v) {
    float lo, hi; asm("mov.b64 {%0,%1},%2;" : "=f"(lo), "=f"(hi) : "l"(v)); return lo;
}
__device__ __forceinline__ float f2hi(u64 v) {
    float lo, hi; asm("mov.b64 {%0,%1},%2;" : "=f"(lo), "=f"(hi) : "l"(v)); return hi;
}
__device__ __forceinline__ uint32_t s2u(const void* p) {
    return (uint32_t)__cvta_generic_to_shared(p);
}
__device__ __forceinline__ void cp16(uint32_t dst, const void* src) {
    asm volatile("cp.async.cg.shared.global [%0], [%1], 16;" :: "r"(dst), "l"(src));
}
#define CP_COMMIT() asm volatile("cp.async.commit_group;")
#define CP_WAIT(n)  asm volatile("cp.async.wait_group %0;" :: "n"(n))

// ---- split-K GEMM partial: part[s][m][c] = sum_{k in split} A[m][k]*W[k][c]
__global__ __launch_bounds__(128, 2)
void gemm_split(const float* __restrict__ A, const float* __restrict__ W,
                float* __restrict__ part, int N)
{
    __shared__ float2 as2[32][KC];
    const int K = 4096;
    const int k0 = blockIdx.y * KC;
    const int c0 = blockIdx.x * 512 + threadIdx.x * 4;

    for (int i = threadIdx.x; i < 32 * KC; i += 128) {
        int m = i >> 7, kk = i & (KC - 1);
        float a = A[m * K + k0 + kk];
        as2[m][kk] = make_float2(a, a);
    }
    __syncthreads();

    u64 acc01[32], acc23[32];
#pragma unroll
    for (int m = 0; m < 32; m++) { acc01[m] = 0ull; acc23[m] = 0ull; }

    const float* Wp = W + (size_t)k0 * N + c0;
    longlong2 wa = *(const longlong2*)Wp;
    longlong2 wb = *(const longlong2*)(Wp + N);
#pragma unroll 1
    for (int kk = 0; kk < KC; kk += 2) {
        const float* Wn  = Wp + 2 * (size_t)N;
        const float* Wsafe = (kk + 2 < KC) ? Wn : Wp;   // avoid OOB prefetch
        longlong2 wa2 = *(const longlong2*)Wsafe;
        longlong2 wb2 = *(const longlong2*)(Wsafe + N);
#pragma unroll
        for (int m = 0; m < 32; m++) {
            const u64* pa = (const u64*)&as2[m][kk];
            u64 a0 = pa[0], a1 = pa[1];
            acc01[m] = ffma2(a0, (u64)wa.x, acc01[m]);
            acc23[m] = ffma2(a0, (u64)wa.y, acc23[m]);
            acc01[m] = ffma2(a1, (u64)wb.x, acc01[m]);
            acc23[m] = ffma2(a1, (u64)wb.y, acc23[m]);
        }
        wa = wa2; wb = wb2; Wp = Wn;
    }

    float* op = part + (size_t)blockIdx.y * 32 * N + c0;
#pragma unroll
    for (int m = 0; m < 32; m++) {
        *(u64*)(op + (size_t)m * N)     = acc01[m];
        *(u64*)(op + (size_t)m * N + 2) = acc23[m];
    }
}

// ---- reduce QKV partials + RoPE; grid (32 rows, 4 col-chunks) -------------
__global__ void qkv_reduce_rope(const int* __restrict__ pos1d)
{
    __shared__ float cs[64], sn[64];
    const int b = blockIdx.x;
    const int tid = threadIdx.x;

    if (tid < 64) {
        float freq = (float)pow(1.0e6, -(double)tid / 64.0);
        float ang = (float)pos1d[b] * freq;
        double sd, cd; sincos((double)ang, &sd, &cd);
        cs[tid] = (float)cd; sn[tid] = (float)sd;
    }
    __syncthreads();

    const int beg = blockIdx.y * 896, end = beg + 896;
    for (int idx = beg + tid; idx < end; idx += 256) {
        if (idx < 2560) {
            int col1, j;
            if (idx < 2048) { int h = idx >> 6; j = idx & 63; col1 = h * 128 + j; }
            else { int t = idx - 2048; int kvh = t >> 6; j = t & 63; col1 = 4096 + kvh * 128 + j; }
            int col2 = col1 + 64;
            float x1 = 0.f, x2 = 0.f;
#pragma unroll
            for (int s = 0; s < S_SPLIT; s++) {
                x1 += g_qkv_part[(s * 32 + b) * 6144 + col1];
                x2 += g_qkv_part[(s * 32 + b) * 6144 + col2];
            }
            float c = cs[j], sv = sn[j];
            g_qkv[b * 6144 + col1] = x1 * c - x2 * sv;
            g_qkv[b * 6144 + col2] = x2 * c + x1 * sv;
        } else {
            int col = 5120 + (idx - 2560);
            float x = 0.f;
#pragma unroll
            for (int s = 0; s < S_SPLIT; s++)
                x += g_qkv_part[(s * 32 + b) * 6144 + col];
            g_qkv[b * 6144 + col] = x;
        }
    }
}

__device__ __forceinline__ float4 warpRedMax4(float4 v) {
#pragma unroll
    for (int o = 16; o > 0; o >>= 1) {
        v.x = fmaxf(v.x, __shfl_xor_sync(0xffffffffu, v.x, o));
        v.y = fmaxf(v.y, __shfl_xor_sync(0xffffffffu, v.y, o));
        v.z = fmaxf(v.z, __shfl_xor_sync(0xffffffffu, v.z, o));
        v.w = fmaxf(v.w, __shfl_xor_sync(0xffffffffu, v.w, o));
    }
    return v;
}
__device__ __forceinline__ float4 warpRedSum4(float4 v) {
#pragma unroll
    for (int o = 16; o > 0; o >>= 1) {
        v.x += __shfl_xor_sync(0xffffffffu, v.x, o);
        v.y += __shfl_xor_sync(0xffffffffu, v.y, o);
        v.z += __shfl_xor_sync(0xffffffffu, v.z, o);
        v.w += __shfl_xor_sync(0xffffffffu, v.w, o);
    }
    return v;
}
__device__ float4 blockRedMax4(float4 v, float4* red) {
    v = warpRedMax4(v);
    int w = threadIdx.x >> 5, lane = threadIdx.x & 31;
    if (lane == 0) red[w] = v;
    __syncthreads();
    if (w == 0) {
        float4 t = (lane < 8) ? red[lane] : make_float4(-1e30f, -1e30f, -1e30f, -1e30f);
        t = warpRedMax4(t);
        if (lane == 0) red[0] = t;
    }
    __syncthreads();
    return red[0];
}
__device__ float4 blockRedSum4(float4 v, float4* red) {
    v = warpRedSum4(v);
    int w = threadIdx.x >> 5, lane = threadIdx.x & 31;
    if (lane == 0) red[w] = v;
    __syncthreads();
    if (w == 0) {
        float4 t = (lane < 8) ? red[lane] : make_float4(0.f, 0.f, 0.f, 0.f);
        t = warpRedSum4(t);
        if (lane == 0) red[0] = t;
    }
    __syncthreads();
    return red[0];
}

// ---- paged GQA attention with cp.async staging ----------------------------
#define TILE_R   16
#define NTILES   256
#define NSTAGE   4
#define STG_F    (TILE_R * 128)
#define ATTN_SMEM ((16384 + 512 + 32 + NSTAGE * STG_F) * 4)

struct TileSrc {
    const float* cache;
    const float* fresh;
};

__device__ __forceinline__ void load_tile(int t, int s, uint32_t stg_u32,
                                          TileSrc src, int posn,
                                          const int* pblk, int kvh, int tid)
{
#pragma unroll
    for (int j = 0; j < 2; j++) {
        int idx = tid + j * 256;
        int row = idx >> 5, ch = idx & 31;
        int l = t * TILE_R + row;
        const float* p;
        if (l == posn) p = src.fresh + ch * 4;
        else {
            int phys = pblk[l >> 6];
            p = src.cache + (((size_t)phys * 64 + (l & 63)) * 8 + kvh) * 128 + ch * 4;
        }
        cp16(stg_u32 + (uint32_t)(s * STG_F + row * 128 + ch * 4) * 4u, p);
    }
    CP_COMMIT();
}

__global__ __launch_bounds__(256, 2)
void attn_kernel(const float* __restrict__ kc, const float* __restrict__ vc,
                 const int* __restrict__ blkoff, const int* __restrict__ kvlens)
{
    extern __shared__ float sm[];
    float* sc  = sm;                     // scores p[l][g], 16384 floats
    float* qp  = sm + 16384;
    float4* red = (float4*)(sm + 16896);
    float* stg = sm + 16928;
    __shared__ int pblk[64];

    const int b = blockIdx.x >> 3, kvh = blockIdx.x & 7;
    const int tid = threadIdx.x;
    const int Lv = kvlens[b];
    const int posn = Lv - 1;
    const float* qkv_b = g_qkv + b * 6144;

    for (int i = tid; i < 512; i += 256) {
        int g = i >> 7, d = i & 127;
        qp[i] = qkv_b[(kvh * 4 + g) * 128 + d] * 0.08838834764831845f;
    }
    if (tid < 64) pblk[tid] = blkoff[b * 64 + tid];
    __syncthreads();

    const uint32_t stg_u32 = s2u(stg);
    TileSrc ksrc = { kc, qkv_b + 4096 + kvh * 128 };
    TileSrc vsrc = { vc, qkv_b + 5120 + kvh * 128 };

    // ---- Phase 1: QK. Warp = 2 rows x 16 lanes; lane covers 8 dims. ------
    const int lane16 = tid & 15;
    const int rw = ((tid >> 4) & 1) + (tid >> 5) * 2;

    float4 qA[4], qB[4];
#pragma unroll
    for (int g = 0; g < 4; g++) {
        qA[g] = *(const float4*)&qp[g * 128 + lane16 * 8];
        qB[g] = *(const float4*)&qp[g * 128 + lane16 * 8 + 4];
    }

#pragma unroll
    for (int t = 0; t < NSTAGE - 1; t++)
        load_tile(t, t, stg_u32, ksrc, posn, pblk, kvh, tid);

    float4 mx = make_float4(-1e30f, -1e30f, -1e30f, -1e30f);
#pragma unroll 1
    for (int t = 0; t < NTILES; t++) {
        CP_WAIT(NSTAGE - 2);
        __syncthreads();
        if (t + NSTAGE - 1 < NTILES)
            load_tile(t + NSTAGE - 1, (t + NSTAGE - 1) & (NSTAGE - 1),
                      stg_u32, ksrc, posn, pblk, kvh, tid);
        else
            CP_COMMIT();                 // empty group: keep wait accounting exact
        const float* kr = stg + (t & (NSTAGE - 1)) * STG_F + rw * 128 + lane16 * 8;
        float4 kA = *(const float4*)kr;
        float4 kB = *(const float4*)(kr + 4);
        float a0, a1, a2, a3;
#define DOT8(g) (kA.x*qA[g].x + kA.y*qA[g].y + kA.z*qA[g].z + kA.w*qA[g].w + \
                 kB.x*qB[g].x + kB.y*qB[g].y + kB.z*qB[g].z + kB.w*qB[g].w)
        a0 = DOT8(0); a1 = DOT8(1); a2 = DOT8(2); a3 = DOT8(3);
#undef DOT8
#pragma unroll
        for (int o = 8; o > 0; o >>= 1) {
            a0 += __shfl_xor_sync(0xffffffffu, a0, o);
            a1 += __shfl_xor_sync(0xffffffffu, a1, o);
            a2 += __shfl_xor_sync(0xffffffffu, a2, o);
            a3 += __shfl_xor_sync(0xffffffffu, a3, o);
        }
        int ll = t * TILE_R + rw;
        if (lane16 == 0) ((float4*)sc)[ll] = make_float4(a0, a1, a2, a3);
        if (ll < Lv) {
            mx.x = fmaxf(mx.x, a0); mx.y = fmaxf(mx.y, a1);
            mx.z = fmaxf(mx.z, a2); mx.w = fmaxf(mx.w, a3);
        }
    }

    // Prefetch V tiles while softmax runs.
    CP_WAIT(0);
    __syncthreads();
#pragma unroll
    for (int t = 0; t < NSTAGE - 1; t++)
        load_tile(t, t, stg_u32, vsrc, posn, pblk, kvh, tid);

    mx = blockRedMax4(mx, red);

    // ---- Phase 2: exp + sum ----------------------------------------------
    float4 sum = make_float4(0.f, 0.f, 0.f, 0.f);
#pragma unroll 1
    for (int i = 0; i < 16; i++) {
        int ll = tid + (i << 8);
        float4 sv = ((float4*)sc)[ll];
        bool valid = (ll < Lv);
        sv.x = valid ? __expf(sv.x - mx.x) : 0.f;
        sv.y = valid ? __expf(sv.y - mx.y) : 0.f;
        sv.z = valid ? __expf(sv.z - mx.z) : 0.f;
        sv.w = valid ? __expf(sv.w - mx.w) : 0.f;
        sum.x += sv.x; sum.y += sv.y; sum.z += sv.z; sum.w += sv.w;
        ((float4*)sc)[ll] = sv;
    }
    __syncthreads();
    sum = blockRedSum4(sum, red);
    float4 inv = make_float4(1.f / sum.x, 1.f / sum.y, 1.f / sum.z, 1.f / sum.w);

    // ---- Phase 3: PV. Warp = 2 rows; lane = d-quad; both g-pairs. --------
    const int d4 = tid & 31;
    const int wv = tid >> 5;
    u64 acc01[4], acc23[4];
#pragma unroll
    for (int j = 0; j < 4; j++) { acc01[j] = 0ull; acc23[j] = 0ull; }

#pragma unroll 1
    for (int t = 0; t < NTILES; t++) {
        CP_WAIT(NSTAGE - 2);
        __syncthreads();
        if (t + NSTAGE - 1 < NTILES)
            load_tile(t + NSTAGE - 1, (t + NSTAGE - 1) & (NSTAGE - 1),
                      stg_u32, vsrc, posn, pblk, kvh, tid);
        else
            CP_COMMIT();                 // empty group: keep wait accounting exact
        const float* vb = stg + (t & (NSTAGE - 1)) * STG_F;
        int r0 = wv * 2, r1 = r0 + 1;
        float4 v0 = *(const float4*)(vb + r0 * 128 + d4 * 4);
        float4 v1 = *(const float4*)(vb + r1 * 128 + d4 * 4);
        int ll0 = t * TILE_R + r0;
        float4 p0 = ((const float4*)sc)[ll0];
        float4 p1 = ((const float4*)sc)[ll0 + 1];
        u64 p0a = f2pack(p0.x, p0.y), p0b = f2pack(p0.z, p0.w);
        u64 p1a = f2pack(p1.x, p1.y), p1b = f2pack(p1.z, p1.w);
        acc01[0] = ffma2(f2pack(v0.x, v0.x), p0a, acc01[0]);
        acc23[0] = ffma2(f2pack(v0.x, v0.x), p0b, acc23[0]);
        acc01[1] = ffma2(f2pack(v0.y, v0.y), p0a, acc01[1]);
        acc23[1] = ffma2(f2pack(v0.y, v0.y), p0b, acc23[1]);
        acc01[2] = ffma2(f2pack(v0.z, v0.z), p0a, acc01[2]);
        acc23[2] = ffma2(f2pack(v0.z, v0.z), p0b, acc23[2]);
        acc01[3] = ffma2(f2pack(v0.w, v0.w), p0a, acc01[3]);
        acc23[3] = ffma2(f2pack(v0.w, v0.w), p0b, acc23[3]);
        acc01[0] = ffma2(f2pack(v1.x, v1.x), p1a, acc01[0]);
        acc23[0] = ffma2(f2pack(v1.x, v1.x), p1b, acc23[0]);
        acc01[1] = ffma2(f2pack(v1.y, v1.y), p1a, acc01[1]);
        acc23[1] = ffma2(f2pack(v1.y, v1.y), p1b, acc23[1]);
        acc01[2] = ffma2(f2pack(v1.z, v1.z), p1a, acc01[2]);
        acc23[2] = ffma2(f2pack(v1.z, v1.z), p1b, acc23[2]);
        acc01[3] = ffma2(f2pack(v1.w, v1.w), p1a, acc01[3]);
        acc23[3] = ffma2(f2pack(v1.w, v1.w), p1b, acc23[3]);
    }
    __syncthreads();
    {
        float* rv = sc + (wv * 32 + d4) * 16;
#pragma unroll
        for (int j = 0; j < 4; j++)
            ((float4*)rv)[j] = make_float4(f2lo(acc01[j]), f2hi(acc01[j]),
                                           f2lo(acc23[j]), f2hi(acc23[j]));
    }
    __syncthreads();
    if (tid < 128) {
        int d4o = tid >> 2, j = tid & 3;
        float4 o = make_float4(0.f, 0.f, 0.f, 0.f);
#pragma unroll
        for (int w = 0; w < 8; w++) {
            float4 pw = ((const float4*)(sc + (w * 32 + d4o) * 16))[j];
            o.x += pw.x; o.y += pw.y; o.z += pw.z; o.w += pw.w;
        }
        int dd = d4o * 4 + j;
        float* ob = g_attn + b * 4096 + kvh * 512;
        ob[0 * 128 + dd] = o.x * inv.x;
        ob[1 * 128 + dd] = o.y * inv.y;
        ob[2 * 128 + dd] = o.z * inv.z;
        ob[3 * 128 + dd] = o.w * inv.w;
    }
}

// ---- final split-K reduction ----------------------------------------------
__global__ void reduce_out(float* __restrict__ out, int n)
{
    int i = blockIdx.x * blockDim.x + threadIdx.x;
    if (i < n) {
        float x = 0.f;
#pragma unroll
        for (int s = 0; s < S_SPLIT; s++) x += g_wo_part[(size_t)s * n + i];
        out[i] = x;
    }
}

extern "C" void kernel_launch(void* const* d_in, const int* in_sizes, int n_in,
                              void* d_out, int out_size)
{
    const float* hidden = (const float*)d_in[0];
    const float* wqkv   = (const float*)d_in[1];
    const float* wo     = (const float*)d_in[2];
    const float* kc     = (const float*)d_in[3];
    const float* vc     = (const float*)d_in[4];
    const int*   pos1d  = (const int*)d_in[5];
    const int*   blkoff = (const int*)d_in[6];
    const int*   kvlens = (const int*)d_in[7];
    float* out = (float*)d_out;

    static bool attr_done = false;
    if (!attr_done) {
        cudaFuncSetAttribute(attn_kernel, cudaFuncAttributeMaxDynamicSharedMemorySize, ATTN_SMEM);
        attr_done = true;
    }

    float *qkv_part, *wo_part, *attn_in;
    cudaGetSymbolAddress((void**)&qkv_part, g_qkv_part);
    cudaGetSymbolAddress((void**)&wo_part,  g_wo_part);
    cudaGetSymbolAddress((void**)&attn_in,  g_attn);

    gemm_split<<<dim3(12, 32), 128>>>(hidden, wqkv, qkv_part, 6144);
    qkv_reduce_rope<<<dim3(32, 4), 256>>>(pos1d);
    attn_kernel<<<256, 256, ATTN_SMEM>>>(kc, vc, blkoff, kvlens);
    gemm_split<<<dim3(8, 32), 128>>>(attn_in, wo, wo_part, 4096);
    reduce_out<<<512, 256>>>(out, 32 * 4096);
}

// round 10
// speedup vs baseline: 1.8542x; 1.0658x over previous
#include <cuda_runtime.h>
#include <math.h>
#include <stdint.h>

typedef unsigned long long u64;

#define S_SPLIT 32
#define KC      128

__device__ float g_qkv_part[S_SPLIT * 32 * 6144];
__device__ float g_qkv[32 * 6144];
__device__ float g_attn[32 * 4096];
__device__ float g_wo_part[S_SPLIT * 32 * 4096];

__device__ __forceinline__ u64 f2pack(float lo, float hi) {
    u64 r; asm("mov.b64 %0,{%1,%2};" : "=l"(r) : "f"(lo), "f"(hi)); return r;
}
__device__ __forceinline__ u64 ffma2(u64 a, u64 b, u64 c) {
    u64 d; asm("fma.rn.f32x2 %0,%1,%2,%3;" : "=l"(d) : "l"(a), "l"(b), "l"(c)); return d;
}
__device__ __forceinline__ u64 fmul2(u64 a, u64 b) {
    u64 d; asm("mul.rn.f32x2 %0,%1,%2;" : "=l"(d) : "l"(a), "l"(b)); return d;
}
__device__ __forceinline__ float f2lo(u64 v) {
    float lo, hi; asm("mov.b64 {%0,%1},%2;" : "=f"(lo), "=f"(hi) : "l"(v)); return lo;
}
__device__ __forceinline__ float f2hi(u64 v) {
    float lo, hi; asm("mov.b64 {%0,%1},%2;" : "=f"(lo), "=f"(hi) : "l"(v)); return hi;
}
__device__ __forceinline__ uint32_t s2u(const void* p) {
    return (uint32_t)__cvta_generic_to_shared(p);
}
__device__ __forceinline__ void cp16(uint32_t dst, const void* src) {
    asm volatile("cp.async.cg.shared.global [%0], [%1], 16;" :: "r"(dst), "l"(src));
}
#define CP_COMMIT() asm volatile("cp.async.commit_group;")
#define CP_WAIT(n)  asm volatile("cp.async.wait_group %0;" :: "n"(n))

// ---- split-K GEMM partial, W prefetch distance 2 ---------------------------
__global__ __launch_bounds__(128, 2)
void gemm_split(const float* __restrict__ A, const float* __restrict__ W,
                float* __restrict__ part, int N)
{
    __shared__ float2 as2[32][KC];
    const int K = 4096;
    const int k0 = blockIdx.y * KC;
    const int c0 = blockIdx.x * 512 + threadIdx.x * 4;

    for (int i = threadIdx.x; i < 32 * KC; i += 128) {
        int m = i >> 7, kk = i & (KC - 1);
        float a = A[m * K + k0 + kk];
        as2[m][kk] = make_float2(a, a);
    }
    __syncthreads();

    u64 acc01[32], acc23[32];
#pragma unroll
    for (int m = 0; m < 32; m++) { acc01[m] = 0ull; acc23[m] = 0ull; }

    const float* Wp = W + (size_t)k0 * N + c0;
    longlong2 wa0 = *(const longlong2*)Wp;
    longlong2 wb0 = *(const longlong2*)(Wp + N);
    longlong2 wa1 = *(const longlong2*)(Wp + 2 * (size_t)N);
    longlong2 wb1 = *(const longlong2*)(Wp + 3 * (size_t)N);
#pragma unroll 1
    for (int kk = 0; kk < KC; kk += 2) {
        const float* Wn = Wp + 4 * (size_t)N;
        const float* Wsafe = (kk + 4 < KC) ? Wn : Wp;     // avoid OOB prefetch
        longlong2 wa2 = *(const longlong2*)Wsafe;
        longlong2 wb2 = *(const longlong2*)(Wsafe + N);
#pragma unroll
        for (int m = 0; m < 32; m++) {
            const u64* pa = (const u64*)&as2[m][kk];
            u64 a0 = pa[0], a1 = pa[1];
            acc01[m] = ffma2(a0, (u64)wa0.x, acc01[m]);
            acc23[m] = ffma2(a0, (u64)wa0.y, acc23[m]);
            acc01[m] = ffma2(a1, (u64)wb0.x, acc01[m]);
            acc23[m] = ffma2(a1, (u64)wb0.y, acc23[m]);
        }
        wa0 = wa1; wb0 = wb1; wa1 = wa2; wb1 = wb2;
        Wp += 2 * (size_t)N;
    }

    float* op = part + (size_t)blockIdx.y * 32 * N + c0;
#pragma unroll
    for (int m = 0; m < 32; m++) {
        *(u64*)(op + (size_t)m * N)     = acc01[m];
        *(u64*)(op + (size_t)m * N + 2) = acc23[m];
    }
}

// ---- reduce QKV partials + RoPE; grid (32 rows, 4 col-chunks) -------------
__global__ void qkv_reduce_rope(const int* __restrict__ pos1d)
{
    __shared__ float cs[64], sn[64];
    const int b = blockIdx.x;
    const int tid = threadIdx.x;

    if (tid < 64) {
        float freq = (float)pow(1.0e6, -(double)tid / 64.0);
        float ang = (float)pos1d[b] * freq;
        double sd, cd; sincos((double)ang, &sd, &cd);
        cs[tid] = (float)cd; sn[tid] = (float)sd;
    }
    __syncthreads();

    const int beg = blockIdx.y * 896, end = beg + 896;
    for (int idx = beg + tid; idx < end; idx += 256) {
        if (idx < 2560) {
            int col1, j;
            if (idx < 2048) { int h = idx >> 6; j = idx & 63; col1 = h * 128 + j; }
            else { int t = idx - 2048; int kvh = t >> 6; j = t & 63; col1 = 4096 + kvh * 128 + j; }
            int col2 = col1 + 64;
            float x1 = 0.f, x2 = 0.f;
#pragma unroll
            for (int s = 0; s < S_SPLIT; s++) {
                x1 += g_qkv_part[(s * 32 + b) * 6144 + col1];
                x2 += g_qkv_part[(s * 32 + b) * 6144 + col2];
            }
            float c = cs[j], sv = sn[j];
            g_qkv[b * 6144 + col1] = x1 * c - x2 * sv;
            g_qkv[b * 6144 + col2] = x2 * c + x1 * sv;
        } else {
            int col = 5120 + (idx - 2560);
            float x = 0.f;
#pragma unroll
            for (int s = 0; s < S_SPLIT; s++)
                x += g_qkv_part[(s * 32 + b) * 6144 + col];
            g_qkv[b * 6144 + col] = x;
        }
    }
}

// ---- flash-decode paged GQA attention -------------------------------------
// CTA = (b, kvh). Tiles of 32 rows, K+V co-staged (32KB/stage), 3 stages.
#define TILE_R   32
#define NTILES   128
#define NSTAGE   3
#define STG_F    (TILE_R * 128 * 2)       // 8192 floats: K tile then V tile
#define ATTN_SMEM ((NSTAGE * STG_F + 512 + 160) * 4)

__device__ __forceinline__ void load_tile(int t, int st, uint32_t stg_u32,
        const float* kc, const float* vc,
        const float* kfresh, const float* vfresh,
        int posn, const int* pblk, int kvh, int tid)
{
    uint32_t base = stg_u32 + (uint32_t)(st * STG_F) * 4u;
#pragma unroll
    for (int j = 0; j < 4; j++) {
        int idx = tid + j * 256;
        int row = idx >> 5, ch = idx & 31;
        int l = t * TILE_R + row;
        const float* p;
        if (l == posn) p = kfresh + ch * 4;
        else {
            int phys = pblk[l >> 6];
            p = kc + (((size_t)phys * 64 + (l & 63)) * 8 + kvh) * 128 + ch * 4;
        }
        cp16(base + (uint32_t)(row * 128 + ch * 4) * 4u, p);
    }
#pragma unroll
    for (int j = 0; j < 4; j++) {
        int idx = tid + j * 256;
        int row = idx >> 5, ch = idx & 31;
        int l = t * TILE_R + row;
        const float* p;
        if (l == posn) p = vfresh + ch * 4;
        else {
            int phys = pblk[l >> 6];
            p = vc + (((size_t)phys * 64 + (l & 63)) * 8 + kvh) * 128 + ch * 4;
        }
        cp16(base + (uint32_t)(TILE_R * 128 + row * 128 + ch * 4) * 4u, p);
    }
    CP_COMMIT();
}

__global__ __launch_bounds__(256, 2)
void attn_kernel(const float* __restrict__ kc, const float* __restrict__ vc,
                 const int* __restrict__ blkoff, const int* __restrict__ kvlens)
{
    extern __shared__ float sm[];
    float* stg  = sm;                          // NSTAGE*STG_F floats
    float* qp   = sm + NSTAGE * STG_F;         // 512
    float* msm  = qp + 512;                    // 32: m[w][g]
    float* ssm  = msm + 32;                    // 32: s[w][g]
    float* wgt  = ssm + 32;                    // 32
    float* invS = wgt + 32;                    // 4
    __shared__ int pblk[64];

    const int b = blockIdx.x >> 3, kvh = blockIdx.x & 7;
    const int tid = threadIdx.x;
    const int Lv = kvlens[b];
    const int posn = Lv - 1;
    const float* qkv_b = g_qkv + b * 6144;

    for (int i = tid; i < 512; i += 256) {
        int g = i >> 7, d = i & 127;
        qp[i] = qkv_b[(kvh * 4 + g) * 128 + d] * 0.08838834764831845f;
    }
    if (tid < 64) pblk[tid] = blkoff[b * 64 + tid];
    __syncthreads();

    const uint32_t stg_u32 = s2u(stg);
    const float* kfresh = qkv_b + 4096 + kvh * 128;
    const float* vfresh = qkv_b + 5120 + kvh * 128;

    const int ln = tid & 31;
    const int wv = tid >> 5;
    const int lane16 = tid & 15;
    const int rsel = (tid >> 4) & 1;

    float4 qA[4], qB[4];
#pragma unroll
    for (int g = 0; g < 4; g++) {
        qA[g] = *(const float4*)&qp[g * 128 + lane16 * 4];
        qB[g] = *(const float4*)&qp[g * 128 + 64 + lane16 * 4];
    }

    load_tile(0, 0, stg_u32, kc, vc, kfresh, vfresh, posn, pblk, kvh, tid);
    load_tile(1, 1, stg_u32, kc, vc, kfresh, vfresh, posn, pblk, kvh, tid);

    float4 m = make_float4(-1e30f, -1e30f, -1e30f, -1e30f);
    float4 s = make_float4(0.f, 0.f, 0.f, 0.f);
    u64 o01[4], o23[4];
#pragma unroll
    for (int j = 0; j < 4; j++) { o01[j] = 0ull; o23[j] = 0ull; }

#pragma unroll 1
    for (int t = 0; t < NTILES; t++) {
        CP_WAIT(1);
        __syncthreads();
        if (t + 2 < NTILES)
            load_tile(t + 2, (t + 2) % NSTAGE, stg_u32, kc, vc, kfresh, vfresh,
                      posn, pblk, kvh, tid);
        else
            CP_COMMIT();                       // empty group keeps wait exact
        const float* kb = stg + (t % NSTAGE) * STG_F;
        const float* vb = kb + TILE_R * 128;

#pragma unroll
        for (int p = 0; p < 2; p++) {
            int r_lo = p * 16 + wv * 2;
            int r = r_lo + rsel;
            const float* kr = kb + r * 128;
            float4 kA = *(const float4*)(kr + lane16 * 4);
            float4 kB = *(const float4*)(kr + 64 + lane16 * 4);
            float a0, a1, a2, a3;
#define DOT8(g) (kA.x*qA[g].x + kA.y*qA[g].y + kA.z*qA[g].z + kA.w*qA[g].w + \
                 kB.x*qB[g].x + kB.y*qB[g].y + kB.z*qB[g].z + kB.w*qB[g].w)
            a0 = DOT8(0); a1 = DOT8(1); a2 = DOT8(2); a3 = DOT8(3);
#undef DOT8
#pragma unroll
            for (int o = 8; o > 0; o >>= 1) {
                a0 += __shfl_xor_sync(0xffffffffu, a0, o);
                a1 += __shfl_xor_sync(0xffffffffu, a1, o);
                a2 += __shfl_xor_sync(0xffffffffu, a2, o);
                a3 += __shfl_xor_sync(0xffffffffu, a3, o);
            }
            if (t * TILE_R + r >= Lv) { a0 = a1 = a2 = a3 = -1e30f; }
            float b0 = __shfl_xor_sync(0xffffffffu, a0, 16);
            float b1 = __shfl_xor_sync(0xffffffffu, a1, 16);
            float b2 = __shfl_xor_sync(0xffffffffu, a2, 16);
            float b3 = __shfl_xor_sync(0xffffffffu, a3, 16);
            float4 alo, ahi;
            alo.x = rsel ? b0 : a0; alo.y = rsel ? b1 : a1;
            alo.z = rsel ? b2 : a2; alo.w = rsel ? b3 : a3;
            ahi.x = rsel ? a0 : b0; ahi.y = rsel ? a1 : b1;
            ahi.z = rsel ? a2 : b2; ahi.w = rsel ? a3 : b3;

            float4 mn;
            mn.x = fmaxf(m.x, fmaxf(alo.x, ahi.x));
            mn.y = fmaxf(m.y, fmaxf(alo.y, ahi.y));
            mn.z = fmaxf(m.z, fmaxf(alo.z, ahi.z));
            mn.w = fmaxf(m.w, fmaxf(alo.w, ahi.w));
            float4 sc4;
            sc4.x = __expf(m.x - mn.x); sc4.y = __expf(m.y - mn.y);
            sc4.z = __expf(m.z - mn.z); sc4.w = __expf(m.w - mn.w);
            float4 plo, phi;
            plo.x = __expf(alo.x - mn.x); plo.y = __expf(alo.y - mn.y);
            plo.z = __expf(alo.z - mn.z); plo.w = __expf(alo.w - mn.w);
            phi.x = __expf(ahi.x - mn.x); phi.y = __expf(ahi.y - mn.y);
            phi.z = __expf(ahi.z - mn.z); phi.w = __expf(ahi.w - mn.w);
            s.x = s.x * sc4.x + plo.x + phi.x;
            s.y = s.y * sc4.y + plo.y + phi.y;
            s.z = s.z * sc4.z + plo.z + phi.z;
            s.w = s.w * sc4.w + plo.w + phi.w;
            m = mn;

            u64 s01 = f2pack(sc4.x, sc4.y), s23 = f2pack(sc4.z, sc4.w);
#pragma unroll
            for (int j = 0; j < 4; j++) {
                o01[j] = fmul2(o01[j], s01);
                o23[j] = fmul2(o23[j], s23);
            }
            u64 plo01 = f2pack(plo.x, plo.y), plo23 = f2pack(plo.z, plo.w);
            u64 phi01 = f2pack(phi.x, phi.y), phi23 = f2pack(phi.z, phi.w);
            float4 vlo = *(const float4*)(vb + r_lo * 128 + ln * 4);
            float4 vhi = *(const float4*)(vb + (r_lo + 1) * 128 + ln * 4);
            o01[0] = ffma2(f2pack(vlo.x, vlo.x), plo01, o01[0]);
            o23[0] = ffma2(f2pack(vlo.x, vlo.x), plo23, o23[0]);
            o01[1] = ffma2(f2pack(vlo.y, vlo.y), plo01, o01[1]);
            o23[1] = ffma2(f2pack(vlo.y, vlo.y), plo23, o23[1]);
            o01[2] = ffma2(f2pack(vlo.z, vlo.z), plo01, o01[2]);
            o23[2] = ffma2(f2pack(vlo.z, vlo.z), plo23, o23[2]);
            o01[3] = ffma2(f2pack(vlo.w, vlo.w), plo01, o01[3]);
            o23[3] = ffma2(f2pack(vlo.w, vlo.w), plo23, o23[3]);
            o01[0] = ffma2(f2pack(vhi.x, vhi.x), phi01, o01[0]);
            o23[0] = ffma2(f2pack(vhi.x, vhi.x), phi23, o23[0]);
            o01[1] = ffma2(f2pack(vhi.y, vhi.y), phi01, o01[1]);
            o23[1] = ffma2(f2pack(vhi.y, vhi.y), phi23, o23[1]);
            o01[2] = ffma2(f2pack(vhi.z, vhi.z), phi01, o01[2]);
            o23[2] = ffma2(f2pack(vhi.z, vhi.z), phi23, o23[2]);
            o01[3] = ffma2(f2pack(vhi.w, vhi.w), phi01, o01[3]);
            o23[3] = ffma2(f2pack(vhi.w, vhi.w), phi23, o23[3]);
        }
    }

    // ---- merge 8 warps' (m, s, o) ----------------------------------------
    __syncthreads();                           // all warps done with staging
    if (ln == 0) {
        msm[wv * 4 + 0] = m.x; msm[wv * 4 + 1] = m.y;
        msm[wv * 4 + 2] = m.z; msm[wv * 4 + 3] = m.w;
        ssm[wv * 4 + 0] = s.x; ssm[wv * 4 + 1] = s.y;
        ssm[wv * 4 + 2] = s.z; ssm[wv * 4 + 3] = s.w;
    }
    float* ov = stg;                           // reuse staging for o partials
#pragma unroll
    for (int j = 0; j < 4; j++)
        ((float4*)(ov + (wv * 32 + ln) * 16))[j] =
            make_float4(f2lo(o01[j]), f2hi(o01[j]), f2lo(o23[j]), f2hi(o23[j]));
    __syncthreads();
    if (tid < 4) {
        int g = tid;
        float M = -1e30f;
#pragma unroll
        for (int w = 0; w < 8; w++) M = fmaxf(M, msm[w * 4 + g]);
        float S = 0.f;
#pragma unroll
        for (int w = 0; w < 8; w++) {
            float e = __expf(msm[w * 4 + g] - M);
            wgt[w * 4 + g] = e;
            S += ssm[w * 4 + g] * e;
        }
        invS[g] = 1.f / S;
    }
    __syncthreads();
    if (tid < 128) {
        int dl = tid >> 2, j = tid & 3;
        int dd = dl * 4 + j;
        float o0 = 0.f, o1 = 0.f, o2 = 0.f, o3 = 0.f;
#pragma unroll
        for (int w = 0; w < 8; w++) {
            float4 pw = ((const float4*)(ov + (w * 32 + dl) * 16))[j];
            o0 += pw.x * wgt[w * 4 + 0];
            o1 += pw.y * wgt[w * 4 + 1];
            o2 += pw.z * wgt[w * 4 + 2];
            o3 += pw.w * wgt[w * 4 + 3];
        }
        float* ob = g_attn + b * 4096 + kvh * 512;
        ob[0 * 128 + dd] = o0 * invS[0];
        ob[1 * 128 + dd] = o1 * invS[1];
        ob[2 * 128 + dd] = o2 * invS[2];
        ob[3 * 128 + dd] = o3 * invS[3];
    }
}

// ---- final split-K reduction ----------------------------------------------
__global__ void reduce_out(float* __restrict__ out, int n)
{
    int i = blockIdx.x * blockDim.x + threadIdx.x;
    if (i < n) {
        float x = 0.f;
#pragma unroll
        for (int s = 0; s < S_SPLIT; s++) x += g_wo_part[(size_t)s * n + i];
        out[i] = x;
    }
}

extern "C" void kernel_launch(void* const* d_in, const int* in_sizes, int n_in,
                              void* d_out, int out_size)
{
    const float* hidden = (const float*)d_in[0];
    const float* wqkv   = (const float*)d_in[1];
    const float* wo     = (const float*)d_in[2];
    const float* kc     = (const float*)d_in[3];
    const float* vc     = (const float*)d_in[4];
    const int*   pos1d  = (const int*)d_in[5];
    const int*   blkoff = (const int*)d_in[6];
    const int*   kvlens = (const int*)d_in[7];
    float* out = (float*)d_out;

    static bool attr_done = false;
    if (!attr_done) {
        cudaFuncSetAttribute(attn_kernel, cudaFuncAttributeMaxDynamicSharedMemorySize, ATTN_SMEM);
        attr_done = true;
    }

    float *qkv_part, *wo_part, *attn_in;
    cudaGetSymbolAddress((void**)&qkv_part, g_qkv_part);
    cudaGetSymbolAddress((void**)&wo_part,  g_wo_part);
    cudaGetSymbolAddress((void**)&attn_in,  g_attn);

    gemm_split<<<dim3(12, 32), 128>>>(hidden, wqkv, qkv_part, 6144);
    qkv_reduce_rope<<<dim3(32, 4), 256>>>(pos1d);
    attn_kernel<<<256, 256, ATTN_SMEM>>>(kc, vc, blkoff, kvlens);
    gemm_split<<<dim3(8, 32), 128>>>(attn_in, wo, wo_part, 4096);
    reduce_out<<<512, 256>>>(out, 32 * 4096);
}

// round 11
// speedup vs baseline: 1.8667x; 1.0067x over previous
#include <cuda_runtime.h>
#include <math.h>
#include <stdint.h>

typedef unsigned long long u64;

#define S_SPLIT 32
#define KC      128

__device__ float g_qkv_part[S_SPLIT * 32 * 6144];
__device__ float g_qkv[32 * 6144];
__device__ float g_attn[32 * 4096];
__device__ float g_wo_part[S_SPLIT * 32 * 4096];

__device__ __forceinline__ u64 f2pack(float lo, float hi) {
    u64 r; asm("mov.b64 %0,{%1,%2};" : "=l"(r) : "f"(lo), "f"(hi)); return r;
}
__device__ __forceinline__ u64 ffma2(u64 a, u64 b, u64 c) {
    u64 d; asm("fma.rn.f32x2 %0,%1,%2,%3;" : "=l"(d) : "l"(a), "l"(b), "l"(c)); return d;
}
__device__ __forceinline__ u64 fmul2(u64 a, u64 b) {
    u64 d; asm("mul.rn.f32x2 %0,%1,%2;" : "=l"(d) : "l"(a), "l"(b)); return d;
}
__device__ __forceinline__ float f2lo(u64 v) {
    float lo, hi; asm("mov.b64 {%0,%1},%2;" : "=f"(lo), "=f"(hi) : "l"(v)); return lo;
}
__device__ __forceinline__ float f2hi(u64 v) {
    float lo, hi; asm("mov.b64 {%0,%1},%2;" : "=f"(lo), "=f"(hi) : "l"(v)); return hi;
}
__device__ __forceinline__ uint32_t s2u(const void* p) {
    return (uint32_t)__cvta_generic_to_shared(p);
}
__device__ __forceinline__ void cp16(uint32_t dst, const void* src) {
    asm volatile("cp.async.cg.shared.global [%0], [%1], 16;" :: "r"(dst), "l"(src));
}
#define CP_COMMIT() asm volatile("cp.async.commit_group;")
#define CP_WAIT(n)  asm volatile("cp.async.wait_group %0;" :: "n"(n))

// ---- split-K GEMM partial, W prefetch distance 2 ---------------------------
__global__ __launch_bounds__(128, 2)
void gemm_split(const float* __restrict__ A, const float* __restrict__ W,
                float* __restrict__ part, int N)
{
    __shared__ float2 as2[32][KC];
    const int K = 4096;
    const int k0 = blockIdx.y * KC;
    const int c0 = blockIdx.x * 512 + threadIdx.x * 4;

    for (int i = threadIdx.x; i < 32 * KC; i += 128) {
        int m = i >> 7, kk = i & (KC - 1);
        float a = A[m * K + k0 + kk];
        as2[m][kk] = make_float2(a, a);
    }
    __syncthreads();

    u64 acc01[32], acc23[32];
#pragma unroll
    for (int m = 0; m < 32; m++) { acc01[m] = 0ull; acc23[m] = 0ull; }

    const float* Wp = W + (size_t)k0 * N + c0;
    longlong2 wa0 = *(const longlong2*)Wp;
    longlong2 wb0 = *(const longlong2*)(Wp + N);
    longlong2 wa1 = *(const longlong2*)(Wp + 2 * (size_t)N);
    longlong2 wb1 = *(const longlong2*)(Wp + 3 * (size_t)N);
#pragma unroll 1
    for (int kk = 0; kk < KC; kk += 2) {
        const float* Wn = Wp + 4 * (size_t)N;
        const float* Wsafe = (kk + 4 < KC) ? Wn : Wp;
        longlong2 wa2 = *(const longlong2*)Wsafe;
        longlong2 wb2 = *(const longlong2*)(Wsafe + N);
#pragma unroll
        for (int m = 0; m < 32; m++) {
            const u64* pa = (const u64*)&as2[m][kk];
            u64 a0 = pa[0], a1 = pa[1];
            acc01[m] = ffma2(a0, (u64)wa0.x, acc01[m]);
            acc23[m] = ffma2(a0, (u64)wa0.y, acc23[m]);
            acc01[m] = ffma2(a1, (u64)wb0.x, acc01[m]);
            acc23[m] = ffma2(a1, (u64)wb0.y, acc23[m]);
        }
        wa0 = wa1; wb0 = wb1; wa1 = wa2; wb1 = wb2;
        Wp += 2 * (size_t)N;
    }

    float* op = part + (size_t)blockIdx.y * 32 * N + c0;
#pragma unroll
    for (int m = 0; m < 32; m++) {
        *(u64*)(op + (size_t)m * N)     = acc01[m];
        *(u64*)(op + (size_t)m * N + 2) = acc23[m];
    }
}

// ---- reduce QKV partials + RoPE; grid (32 rows, 4 col-chunks) -------------
__global__ void qkv_reduce_rope(const int* __restrict__ pos1d)
{
    __shared__ float cs[64], sn[64];
    const int b = blockIdx.x;
    const int tid = threadIdx.x;

    if (tid < 64) {
        float freq = (float)pow(1.0e6, -(double)tid / 64.0);
        float ang = (float)pos1d[b] * freq;
        double sd, cd; sincos((double)ang, &sd, &cd);
        cs[tid] = (float)cd; sn[tid] = (float)sd;
    }
    __syncthreads();

    const int beg = blockIdx.y * 896, end = beg + 896;
    for (int idx = beg + tid; idx < end; idx += 256) {
        if (idx < 2560) {
            int col1, j;
            if (idx < 2048) { int h = idx >> 6; j = idx & 63; col1 = h * 128 + j; }
            else { int t = idx - 2048; int kvh = t >> 6; j = t & 63; col1 = 4096 + kvh * 128 + j; }
            int col2 = col1 + 64;
            float x1 = 0.f, x2 = 0.f;
#pragma unroll
            for (int s = 0; s < S_SPLIT; s++) {
                x1 += g_qkv_part[(s * 32 + b) * 6144 + col1];
                x2 += g_qkv_part[(s * 32 + b) * 6144 + col2];
            }
            float c = cs[j], sv = sn[j];
            g_qkv[b * 6144 + col1] = x1 * c - x2 * sv;
            g_qkv[b * 6144 + col2] = x2 * c + x1 * sv;
        } else {
            int col = 5120 + (idx - 2560);
            float x = 0.f;
#pragma unroll
            for (int s = 0; s < S_SPLIT; s++)
                x += g_qkv_part[(s * 32 + b) * 6144 + col];
            g_qkv[b * 6144 + col] = x;
        }
    }
}

// ---- flash-decode paged GQA attention, per-warp cp.async pipelines --------
// CTA = (b, kvh), 256 threads. Warp w owns rows [w*512, w*512+512).
// Step = 4 rows: stage holds 4 K-rows + 4 V-rows, each padded to 132 floats.
#define W_STEPS  128
#define ROW_F    132
#define STG_FL   (8 * ROW_F)                  // 1056 floats per stage
#define WNSTAGE  3
#define WARP_STG (WNSTAGE * STG_FL)           // 3168 floats per warp
#define ATTN_SMEM ((8 * WARP_STG + 512 + 104) * 4)

__global__ __launch_bounds__(256, 2)
void attn_kernel(const float* __restrict__ kc, const float* __restrict__ vc,
                 const int* __restrict__ blkoff, const int* __restrict__ kvlens)
{
    extern __shared__ float sm[];
    float* stg  = sm;                          // 8 * WARP_STG
    float* qp   = sm + 8 * WARP_STG;           // 512
    float* msm  = qp + 512;                    // 32
    float* ssm  = msm + 32;                    // 32
    float* wgt  = ssm + 32;                    // 32
    float* invS = wgt + 32;                    // 4
    __shared__ int pblk[64];

    const int b = blockIdx.x >> 3, kvh = blockIdx.x & 7;
    const int tid = threadIdx.x;
    const int Lv = kvlens[b];
    const int posn = Lv - 1;
    const float* qkv_b = g_qkv + b * 6144;

    for (int i = tid; i < 512; i += 256) {
        int g = i >> 7, d = i & 127;
        qp[i] = qkv_b[(kvh * 4 + g) * 128 + d] * 0.08838834764831845f;
    }
    if (tid < 64) pblk[tid] = blkoff[b * 64 + tid];
    __syncthreads();

    const int wv = tid >> 5, ln = tid & 31;
    const int lane16 = ln & 15, half = ln >> 4;
    const int rbase = wv * 512;               // warp's first row
    float* wstg = stg + wv * WARP_STG;
    const uint32_t wstg_u32 = s2u(wstg);
    const float* kfresh = qkv_b + 4096 + kvh * 128;
    const float* vfresh = qkv_b + 5120 + kvh * 128;

    float4 qA[4], qB[4];
#pragma unroll
    for (int g = 0; g < 4; g++) {
        qA[g] = *(const float4*)&qp[g * 128 + lane16 * 4];
        qB[g] = *(const float4*)&qp[g * 128 + 64 + lane16 * 4];
    }

    // per-warp step loader: 4 K-rows then 4 V-rows, 8 cp16 per lane
#define LOAD_STEP(st, slot)                                                     \
    do {                                                                        \
        uint32_t sb = wstg_u32 + (uint32_t)((slot) * STG_FL) * 4u;              \
        _Pragma("unroll")                                                       \
        for (int j = 0; j < 8; j++) {                                           \
            int l = rbase + (st) * 4 + (j & 3);                                 \
            const float* cache = (j < 4) ? kc : vc;                             \
            const float* fr    = (j < 4) ? kfresh : vfresh;                     \
            const float* src;                                                   \
            if (l == posn) src = fr + ln * 4;                                   \
            else {                                                              \
                int phys = pblk[l >> 6];                                        \
                src = cache + (((size_t)phys * 64 + (l & 63)) * 8 + kvh) * 128  \
                      + ln * 4;                                                 \
            }                                                                   \
            cp16(sb + (uint32_t)(j * ROW_F + ln * 4) * 4u, src);                \
        }                                                                       \
        CP_COMMIT();                                                            \
    } while (0)

    LOAD_STEP(0, 0);
    LOAD_STEP(1, 1);

    float4 m = make_float4(-1e30f, -1e30f, -1e30f, -1e30f);
    float4 s = make_float4(0.f, 0.f, 0.f, 0.f);
    u64 o01[4], o23[4];
#pragma unroll
    for (int j = 0; j < 4; j++) { o01[j] = 0ull; o23[j] = 0ull; }

#pragma unroll 1
    for (int t = 0; t < W_STEPS; t++) {
        __syncwarp();                          // lanes done reading slot being rewritten
        if (t + 2 < W_STEPS) LOAD_STEP(t + 2, (t + 2) % WNSTAGE);
        else CP_COMMIT();                      // empty group keeps wait exact
        CP_WAIT(2);
        __syncwarp();
        const float* kb = wstg + (t % WNSTAGE) * STG_FL;
        const float* vb = kb + 4 * ROW_F;

        // QK: two sub-passes; this thread handles row (pass*2 + half)
        float4 sA, sB;
#pragma unroll
        for (int pass = 0; pass < 2; pass++) {
            int r = pass * 2 + half;
            const float* kr = kb + r * ROW_F;
            float4 kA = *(const float4*)(kr + lane16 * 4);
            float4 kB = *(const float4*)(kr + 64 + lane16 * 4);
            float a0, a1, a2, a3;
#define DOT8(g) (kA.x*qA[g].x + kA.y*qA[g].y + kA.z*qA[g].z + kA.w*qA[g].w + \
                 kB.x*qB[g].x + kB.y*qB[g].y + kB.z*qB[g].z + kB.w*qB[g].w)
            a0 = DOT8(0); a1 = DOT8(1); a2 = DOT8(2); a3 = DOT8(3);
#undef DOT8
#pragma unroll
            for (int o = 8; o > 0; o >>= 1) {
                a0 += __shfl_xor_sync(0xffffffffu, a0, o);
                a1 += __shfl_xor_sync(0xffffffffu, a1, o);
                a2 += __shfl_xor_sync(0xffffffffu, a2, o);
                a3 += __shfl_xor_sync(0xffffffffu, a3, o);
            }
            if (rbase + t * 4 + r >= Lv) { a0 = a1 = a2 = a3 = -1e30f; }
            if (pass == 0) sA = make_float4(a0, a1, a2, a3);
            else           sB = make_float4(a0, a1, a2, a3);
        }
        // exchange halves: other half's rows
        float4 tA, tB;
        tA.x = __shfl_xor_sync(0xffffffffu, sA.x, 16);
        tA.y = __shfl_xor_sync(0xffffffffu, sA.y, 16);
        tA.z = __shfl_xor_sync(0xffffffffu, sA.z, 16);
        tA.w = __shfl_xor_sync(0xffffffffu, sA.w, 16);
        tB.x = __shfl_xor_sync(0xffffffffu, sB.x, 16);
        tB.y = __shfl_xor_sync(0xffffffffu, sB.y, 16);
        tB.z = __shfl_xor_sync(0xffffffffu, sB.z, 16);
        tB.w = __shfl_xor_sync(0xffffffffu, sB.w, 16);
        float4 r0 = half ? tA : sA;            // row 0
        float4 r1 = half ? sA : tA;            // row 1
        float4 r2 = half ? tB : sB;            // row 2
        float4 r3 = half ? sB : tB;            // row 3

        // online softmax update
        float4 mn;
        mn.x = fmaxf(fmaxf(fmaxf(r0.x, r1.x), fmaxf(r2.x, r3.x)), m.x);
        mn.y = fmaxf(fmaxf(fmaxf(r0.y, r1.y), fmaxf(r2.y, r3.y)), m.y);
        mn.z = fmaxf(fmaxf(fmaxf(r0.z, r1.z), fmaxf(r2.z, r3.z)), m.z);
        mn.w = fmaxf(fmaxf(fmaxf(r0.w, r1.w), fmaxf(r2.w, r3.w)), m.w);
        float4 sc4;
        sc4.x = __expf(m.x - mn.x); sc4.y = __expf(m.y - mn.y);
        sc4.z = __expf(m.z - mn.z); sc4.w = __expf(m.w - mn.w);
        float4 p0, p1, p2, p3;
        p0.x = __expf(r0.x - mn.x); p0.y = __expf(r0.y - mn.y);
        p0.z = __expf(r0.z - mn.z); p0.w = __expf(r0.w - mn.w);
        p1.x = __expf(r1.x - mn.x); p1.y = __expf(r1.y - mn.y);
        p1.z = __expf(r1.z - mn.z); p1.w = __expf(r1.w - mn.w);
        p2.x = __expf(r2.x - mn.x); p2.y = __expf(r2.y - mn.y);
        p2.z = __expf(r2.z - mn.z); p2.w = __expf(r2.w - mn.w);
        p3.x = __expf(r3.x - mn.x); p3.y = __expf(r3.y - mn.y);
        p3.z = __expf(r3.z - mn.z); p3.w = __expf(r3.w - mn.w);
        s.x = s.x * sc4.x + p0.x + p1.x + p2.x + p3.x;
        s.y = s.y * sc4.y + p0.y + p1.y + p2.y + p3.y;
        s.z = s.z * sc4.z + p0.z + p1.z + p2.z + p3.z;
        s.w = s.w * sc4.w + p0.w + p1.w + p2.w + p3.w;
        m = mn;

        u64 s01 = f2pack(sc4.x, sc4.y), s23 = f2pack(sc4.z, sc4.w);
#pragma unroll
        for (int j = 0; j < 4; j++) {
            o01[j] = fmul2(o01[j], s01);
            o23[j] = fmul2(o23[j], s23);
        }
        // PV: this lane's 4 dims for all 4 rows
        float4 v0 = *(const float4*)(vb + 0 * ROW_F + ln * 4);
        float4 v1 = *(const float4*)(vb + 1 * ROW_F + ln * 4);
        float4 v2 = *(const float4*)(vb + 2 * ROW_F + ln * 4);
        float4 v3 = *(const float4*)(vb + 3 * ROW_F + ln * 4);
#define PVROW(vv, pp)                                                    \
        do {                                                             \
            u64 q01 = f2pack(pp.x, pp.y), q23 = f2pack(pp.z, pp.w);      \
            o01[0] = ffma2(f2pack(vv.x, vv.x), q01, o01[0]);             \
            o23[0] = ffma2(f2pack(vv.x, vv.x), q23, o23[0]);             \
            o01[1] = ffma2(f2pack(vv.y, vv.y), q01, o01[1]);             \
            o23[1] = ffma2(f2pack(vv.y, vv.y), q23, o23[1]);             \
            o01[2] = ffma2(f2pack(vv.z, vv.z), q01, o01[2]);             \
            o23[2] = ffma2(f2pack(vv.z, vv.z), q23, o23[2]);             \
            o01[3] = ffma2(f2pack(vv.w, vv.w), q01, o01[3]);             \
            o23[3] = ffma2(f2pack(vv.w, vv.w), q23, o23[3]);             \
        } while (0)
        PVROW(v0, p0); PVROW(v1, p1); PVROW(v2, p2); PVROW(v3, p3);
#undef PVROW
    }
    CP_WAIT(0);

    // ---- merge 8 warps' (m, s, o) ----------------------------------------
    __syncthreads();
    if (ln == 0) {
        msm[wv * 4 + 0] = m.x; msm[wv * 4 + 1] = m.y;
        msm[wv * 4 + 2] = m.z; msm[wv * 4 + 3] = m.w;
        ssm[wv * 4 + 0] = s.x; ssm[wv * 4 + 1] = s.y;
        ssm[wv * 4 + 2] = s.z; ssm[wv * 4 + 3] = s.w;
    }
    float* ov = stg;                           // reuse staging for o partials
#pragma unroll
    for (int j = 0; j < 4; j++)
        ((float4*)(ov + (wv * 32 + ln) * 16))[j] =
            make_float4(f2lo(o01[j]), f2hi(o01[j]), f2lo(o23[j]), f2hi(o23[j]));
    __syncthreads();
    if (tid < 4) {
        int g = tid;
        float M = -1e30f;
#pragma unroll
        for (int w = 0; w < 8; w++) M = fmaxf(M, msm[w * 4 + g]);
        float S = 0.f;
#pragma unroll
        for (int w = 0; w < 8; w++) {
            float e = __expf(msm[w * 4 + g] - M);
            wgt[w * 4 + g] = e;
            S += ssm[w * 4 + g] * e;
        }
        invS[g] = 1.f / S;
    }
    __syncthreads();
    if (tid < 128) {
        int dl = tid >> 2, j = tid & 3;
        int dd = dl * 4 + j;
        float o0 = 0.f, o1 = 0.f, o2 = 0.f, o3 = 0.f;
#pragma unroll
        for (int w = 0; w < 8; w++) {
            float4 pw = ((const float4*)(ov + (w * 32 + dl) * 16))[j];
            o0 += pw.x * wgt[w * 4 + 0];
            o1 += pw.y * wgt[w * 4 + 1];
            o2 += pw.z * wgt[w * 4 + 2];
            o3 += pw.w * wgt[w * 4 + 3];
        }
        float* ob = g_attn + b * 4096 + kvh * 512;
        ob[0 * 128 + dd] = o0 * invS[0];
        ob[1 * 128 + dd] = o1 * invS[1];
        ob[2 * 128 + dd] = o2 * invS[2];
        ob[3 * 128 + dd] = o3 * invS[3];
    }
}

// ---- final split-K reduction ----------------------------------------------
__global__ void reduce_out(float* __restrict__ out, int n)
{
    int i = blockIdx.x * blockDim.x + threadIdx.x;
    if (i < n) {
        float x = 0.f;
#pragma unroll
        for (int s = 0; s < S_SPLIT; s++) x += g_wo_part[(size_t)s * n + i];
        out[i] = x;
    }
}

extern "C" void kernel_launch(void* const* d_in, const int* in_sizes, int n_in,
                              void* d_out, int out_size)
{
    const float* hidden = (const float*)d_in[0];
    const float* wqkv   = (const float*)d_in[1];
    const float* wo     = (const float*)d_in[2];
    const float* kc     = (const float*)d_in[3];
    const float* vc     = (const float*)d_in[4];
    const int*   pos1d  = (const int*)d_in[5];
    const int*   blkoff = (const int*)d_in[6];
    const int*   kvlens = (const int*)d_in[7];
    float* out = (float*)d_out;

    static bool attr_done = false;
    if (!attr_done) {
        cudaFuncSetAttribute(attn_kernel, cudaFuncAttributeMaxDynamicSharedMemorySize, ATTN_SMEM);
        attr_done = true;
    }

    float *qkv_part, *wo_part, *attn_in;
    cudaGetSymbolAddress((void**)&qkv_part, g_qkv_part);
    cudaGetSymbolAddress((void**)&wo_part,  g_wo_part);
    cudaGetSymbolAddress((void**)&attn_in,  g_attn);

    gemm_split<<<dim3(12, 32), 128>>>(hidden, wqkv, qkv_part, 6144);
    qkv_reduce_rope<<<dim3(32, 4), 256>>>(pos1d);
    attn_kernel<<<256, 256, ATTN_SMEM>>>(kc, vc, blkoff, kvlens);
    gemm_split<<<dim3(8, 32), 128>>>(attn_in, wo, wo_part, 4096);
    reduce_out<<<512, 256>>>(out, 32 * 4096);
}

// round 13
// speedup vs baseline: 2.0233x; 1.0839x over previous
#include <cuda_runtime.h>
#include <math.h>
#include <stdint.h>

typedef unsigned long long u64;

#define S_SPLIT 32
#define KC      128

__device__ float g_qkv_part[S_SPLIT * 32 * 6144];
__device__ float g_qkv[32 * 6144];
__device__ float g_attn[32 * 4096];
__device__ float g_wo_part[S_SPLIT * 32 * 4096];

__device__ __forceinline__ u64 f2pack(float lo, float hi) {
    u64 r; asm("mov.b64 %0,{%1,%2};" : "=l"(r) : "f"(lo), "f"(hi)); return r;
}
__device__ __forceinline__ u64 ffma2(u64 a, u64 b, u64 c) {
    u64 d; asm("fma.rn.f32x2 %0,%1,%2,%3;" : "=l"(d) : "l"(a), "l"(b), "l"(c)); return d;
}
__device__ __forceinline__ u64 fmul2(u64 a, u64 b) {
    u64 d; asm("mul.rn.f32x2 %0,%1,%2;" : "=l"(d) : "l"(a), "l"(b)); return d;
}
__device__ __forceinline__ float f2lo(u64 v) {
    float lo, hi; asm("mov.b64 {%0,%1},%2;" : "=f"(lo), "=f"(hi) : "l"(v)); return lo;
}
__device__ __forceinline__ float f2hi(u64 v) {
    float lo, hi; asm("mov.b64 {%0,%1},%2;" : "=f"(lo), "=f"(hi) : "l"(v)); return hi;
}
__device__ __forceinline__ uint32_t s2u(const void* p) {
    return (uint32_t)__cvta_generic_to_shared(p);
}
__device__ __forceinline__ void cp16(uint32_t dst, const void* src) {
    asm volatile("cp.async.cg.shared.global [%0], [%1], 16;" :: "r"(dst), "l"(src));
}
#define CP_COMMIT() asm volatile("cp.async.commit_group;")
#define CP_WAIT(n)  asm volatile("cp.async.wait_group %0;" :: "n"(n))

// ---- noop: shifts ncu capture point so launch #6 is attn_kernel -----------
__global__ void noop_kernel() {}

// ---- split-K GEMM partial with cp.async W staging -------------------------
// Stage = 2 W-rows x 512 cols (4KB). 4 stages. Thread t writes & reads only
// its own 16B per row => no __syncthreads in the main loop.
#define GNST 4
__global__ __launch_bounds__(128, 2)
void gemm_split(const float* __restrict__ A, const float* __restrict__ W,
                float* __restrict__ part, int N)
{
    __shared__ float2 as2[32][KC];          // 32768 B
    __shared__ float  wstg[GNST][1024];     // 16384 B  (total exactly 48KB)
    const int K = 4096;
    const int k0 = blockIdx.y * KC;
    const int tid = threadIdx.x;

    for (int i = tid; i < 32 * KC; i += 128) {
        int m = i >> 7, kk = i & (KC - 1);
        float a = A[m * K + k0 + kk];
        as2[m][kk] = make_float2(a, a);
    }

    const uint32_t wbase = s2u(wstg);
    const float* Wrow = W + (size_t)k0 * N + blockIdx.x * 512 + tid * 4;
#pragma unroll
    for (int s = 0; s < GNST - 1; s++) {    // stages for iters 0,1,2
        cp16(wbase + (uint32_t)((s * 1024 +   0) + tid * 4) * 4u,
             Wrow + (size_t)(2 * s) * N);
        cp16(wbase + (uint32_t)((s * 1024 + 512) + tid * 4) * 4u,
             Wrow + (size_t)(2 * s + 1) * N);
        CP_COMMIT();
    }
    __syncthreads();                        // as2 ready

    u64 acc01[32], acc23[32];
#pragma unroll
    for (int m = 0; m < 32; m++) { acc01[m] = 0ull; acc23[m] = 0ull; }

#pragma unroll 1
    for (int it = 0; it < 64; it++) {
        CP_WAIT(2);                          // stage 'it' resident (self-written)
        const float* ws = wstg[it & (GNST - 1)];
        u64 wa0 = *(const u64*)(ws + tid * 4);
        u64 wa1 = *(const u64*)(ws + tid * 4 + 2);
        u64 wb0 = *(const u64*)(ws + 512 + tid * 4);
        u64 wb1 = *(const u64*)(ws + 512 + tid * 4 + 2);
        if (it + GNST - 1 < 64) {
            int s = (it + GNST - 1) & (GNST - 1);
            cp16(wbase + (uint32_t)((s * 1024 +   0) + tid * 4) * 4u,
                 Wrow + (size_t)(2 * (it + GNST - 1)) * N);
            cp16(wbase + (uint32_t)((s * 1024 + 512) + tid * 4) * 4u,
                 Wrow + (size_t)(2 * (it + GNST - 1) + 1) * N);
            CP_COMMIT();
        } else {
            CP_COMMIT();                     // empty group keeps wait exact
        }
        const int kk = 2 * it;
#pragma unroll
        for (int m = 0; m < 32; m++) {
            const u64* pa = (const u64*)&as2[m][kk];
            u64 a0 = pa[0], a1 = pa[1];
            acc01[m] = ffma2(a0, wa0, acc01[m]);
            acc23[m] = ffma2(a0, wa1, acc23[m]);
            acc01[m] = ffma2(a1, wb0, acc01[m]);
            acc23[m] = ffma2(a1, wb1, acc23[m]);
        }
    }

    float* op = part + (size_t)blockIdx.y * 32 * N + blockIdx.x * 512 + tid * 4;
#pragma unroll
    for (int m = 0; m < 32; m++) {
        *(u64*)(op + (size_t)m * N)     = acc01[m];
        *(u64*)(op + (size_t)m * N + 2) = acc23[m];
    }
}

// ---- reduce QKV partials + RoPE; grid (32 rows, 4 col-chunks) -------------
__global__ void qkv_reduce_rope(const int* __restrict__ pos1d)
{
    __shared__ float cs[64], sn[64];
    const int b = blockIdx.x;
    const int tid = threadIdx.x;

    if (tid < 64) {
        float freq = (float)pow(1.0e6, -(double)tid / 64.0);
        float ang = (float)pos1d[b] * freq;
        double sd, cd; sincos((double)ang, &sd, &cd);
        cs[tid] = (float)cd; sn[tid] = (float)sd;
    }
    __syncthreads();

    const int beg = blockIdx.y * 896, end = beg + 896;
    for (int idx = beg + tid; idx < end; idx += 256) {
        if (idx < 2560) {
            int col1, j;
            if (idx < 2048) { int h = idx >> 6; j = idx & 63; col1 = h * 128 + j; }
            else { int t = idx - 2048; int kvh = t >> 6; j = t & 63; col1 = 4096 + kvh * 128 + j; }
            int col2 = col1 + 64;
            float x1 = 0.f, x2 = 0.f;
#pragma unroll
            for (int s = 0; s < S_SPLIT; s++) {
                x1 += g_qkv_part[(s * 32 + b) * 6144 + col1];
                x2 += g_qkv_part[(s * 32 + b) * 6144 + col2];
            }
            float c = cs[j], sv = sn[j];
            g_qkv[b * 6144 + col1] = x1 * c - x2 * sv;
            g_qkv[b * 6144 + col2] = x2 * c + x1 * sv;
        } else {
            int col = 5120 + (idx - 2560);
            float x = 0.f;
#pragma unroll
            for (int s = 0; s < S_SPLIT; s++)
                x += g_qkv_part[(s * 32 + b) * 6144 + col];
            g_qkv[b * 6144 + col] = x;
        }
    }
}

// ---- flash-decode paged GQA attention, per-warp cp.async pipelines --------
#define W_STEPS  128
#define ROW_F    132
#define STG_FL   (8 * ROW_F)
#define WNSTAGE  3
#define WARP_STG (WNSTAGE * STG_FL)
#define ATTN_SMEM ((8 * WARP_STG + 512 + 104) * 4)

__global__ __launch_bounds__(256, 2)
void attn_kernel(const float* __restrict__ kc, const float* __restrict__ vc,
                 const int* __restrict__ blkoff, const int* __restrict__ kvlens)
{
    extern __shared__ float sm[];
    float* stg  = sm;
    float* qp   = sm + 8 * WARP_STG;
    float* msm  = qp + 512;
    float* ssm  = msm + 32;
    float* wgt  = ssm + 32;
    float* invS = wgt + 32;
    __shared__ int pblk[64];

    const int b = blockIdx.x >> 3, kvh = blockIdx.x & 7;
    const int tid = threadIdx.x;
    const int Lv = kvlens[b];
    const int posn = Lv - 1;
    const float* qkv_b = g_qkv + b * 6144;

    for (int i = tid; i < 512; i += 256) {
        int g = i >> 7, d = i & 127;
        qp[i] = qkv_b[(kvh * 4 + g) * 128 + d] * 0.08838834764831845f;
    }
    if (tid < 64) pblk[tid] = blkoff[b * 64 + tid];
    __syncthreads();

    const int wv = tid >> 5, ln = tid & 31;
    const int lane16 = ln & 15, half = ln >> 4;
    const int rbase = wv * 512;
    float* wstg = stg + wv * WARP_STG;
    const uint32_t wstg_u32 = s2u(wstg);
    const float* kfresh = qkv_b + 4096 + kvh * 128;
    const float* vfresh = qkv_b + 5120 + kvh * 128;

    float4 qA[4], qB[4];
#pragma unroll
    for (int g = 0; g < 4; g++) {
        qA[g] = *(const float4*)&qp[g * 128 + lane16 * 4];
        qB[g] = *(const float4*)&qp[g * 128 + 64 + lane16 * 4];
    }

#define LOAD_STEP(st, slot)                                                     \
    do {                                                                        \
        uint32_t sb = wstg_u32 + (uint32_t)((slot) * STG_FL) * 4u;              \
        _Pragma("unroll")                                                       \
        for (int j = 0; j < 8; j++) {                                           \
            int l = rbase + (st) * 4 + (j & 3);                                 \
            const float* cache = (j < 4) ? kc : vc;                             \
            const float* fr    = (j < 4) ? kfresh : vfresh;                     \
            const float* src;                                                   \
            if (l == posn) src = fr + ln * 4;                                   \
            else {                                                              \
                int phys = pblk[l >> 6];                                        \
                src = cache + (((size_t)phys * 64 + (l & 63)) * 8 + kvh) * 128  \
                      + ln * 4;                                                 \
            }                                                                   \
            cp16(sb + (uint32_t)(j * ROW_F + ln * 4) * 4u, src);                \
        }                                                                       \
        CP_COMMIT();                                                            \
    } while (0)

    LOAD_STEP(0, 0);
    LOAD_STEP(1, 1);

    float4 m = make_float4(-1e30f, -1e30f, -1e30f, -1e30f);
    float4 s = make_float4(0.f, 0.f, 0.f, 0.f);
    u64 o01[4], o23[4];
#pragma unroll
    for (int j = 0; j < 4; j++) { o01[j] = 0ull; o23[j] = 0ull; }

#pragma unroll 1
    for (int t = 0; t < W_STEPS; t++) {
        __syncwarp();
        if (t + 2 < W_STEPS) LOAD_STEP(t + 2, (t + 2) % WNSTAGE);
        else CP_COMMIT();
        CP_WAIT(2);
        __syncwarp();
        const float* kb = wstg + (t % WNSTAGE) * STG_FL;
        const float* vb = kb + 4 * ROW_F;

        float4 sA, sB;
#pragma unroll
        for (int pass = 0; pass < 2; pass++) {
            int r = pass * 2 + half;
            const float* kr = kb + r * ROW_F;
            float4 kA = *(const float4*)(kr + lane16 * 4);
            float4 kB = *(const float4*)(kr + 64 + lane16 * 4);
            float a0, a1, a2, a3;
#define DOT8(g) (kA.x*qA[g].x + kA.y*qA[g].y + kA.z*qA[g].z + kA.w*qA[g].w + \
                 kB.x*qB[g].x + kB.y*qB[g].y + kB.z*qB[g].z + kB.w*qB[g].w)
            a0 = DOT8(0); a1 = DOT8(1); a2 = DOT8(2); a3 = DOT8(3);
#undef DOT8
#pragma unroll
            for (int o = 8; o > 0; o >>= 1) {
                a0 += __shfl_xor_sync(0xffffffffu, a0, o);
                a1 += __shfl_xor_sync(0xffffffffu, a1, o);
                a2 += __shfl_xor_sync(0xffffffffu, a2, o);
                a3 += __shfl_xor_sync(0xffffffffu, a3, o);
            }
            if (rbase + t * 4 + r >= Lv) { a0 = a1 = a2 = a3 = -1e30f; }
            if (pass == 0) sA = make_float4(a0, a1, a2, a3);
            else           sB = make_float4(a0, a1, a2, a3);
        }
        float4 tA, tB;
        tA.x = __shfl_xor_sync(0xffffffffu, sA.x, 16);
        tA.y = __shfl_xor_sync(0xffffffffu, sA.y, 16);
        tA.z = __shfl_xor_sync(0xffffffffu, sA.z, 16);
        tA.w = __shfl_xor_sync(0xffffffffu, sA.w, 16);
        tB.x = __shfl_xor_sync(0xffffffffu, sB.x, 16);
        tB.y = __shfl_xor_sync(0xffffffffu, sB.y, 16);
        tB.z = __shfl_xor_sync(0xffffffffu, sB.z, 16);
        tB.w = __shfl_xor_sync(0xffffffffu, sB.w, 16);
        float4 r0 = half ? tA : sA;
        float4 r1 = half ? sA : tA;
        float4 r2 = half ? tB : sB;
        float4 r3 = half ? sB : tB;

        float4 mn;
        mn.x = fmaxf(fmaxf(fmaxf(r0.x, r1.x), fmaxf(r2.x, r3.x)), m.x);
        mn.y = fmaxf(fmaxf(fmaxf(r0.y, r1.y), fmaxf(r2.y, r3.y)), m.y);
        mn.z = fmaxf(fmaxf(fmaxf(r0.z, r1.z), fmaxf(r2.z, r3.z)), m.z);
        mn.w = fmaxf(fmaxf(fmaxf(r0.w, r1.w), fmaxf(r2.w, r3.w)), m.w);
        float4 sc4;
        sc4.x = __expf(m.x - mn.x); sc4.y = __expf(m.y - mn.y);
        sc4.z = __expf(m.z - mn.z); sc4.w = __expf(m.w - mn.w);
        float4 p0, p1, p2, p3;
        p0.x = __expf(r0.x - mn.x); p0.y = __expf(r0.y - mn.y);
        p0.z = __expf(r0.z - mn.z); p0.w = __expf(r0.w - mn.w);
        p1.x = __expf(r1.x - mn.x); p1.y = __expf(r1.y - mn.y);
        p1.z = __expf(r1.z - mn.z); p1.w = __expf(r1.w - mn.w);
        p2.x = __expf(r2.x - mn.x); p2.y = __expf(r2.y - mn.y);
        p2.z = __expf(r2.z - mn.z); p2.w = __expf(r2.w - mn.w);
        p3.x = __expf(r3.x - mn.x); p3.y = __expf(r3.y - mn.y);
        p3.z = __expf(r3.z - mn.z); p3.w = __expf(r3.w - mn.w);
        s.x = s.x * sc4.x + p0.x + p1.x + p2.x + p3.x;
        s.y = s.y * sc4.y + p0.y + p1.y + p2.y + p3.y;
        s.z = s.z * sc4.z + p0.z + p1.z + p2.z + p3.z;
        s.w = s.w * sc4.w + p0.w + p1.w + p2.w + p3.w;
        m = mn;

        u64 s01 = f2pack(sc4.x, sc4.y), s23 = f2pack(sc4.z, sc4.w);
#pragma unroll
        for (int j = 0; j < 4; j++) {
            o01[j] = fmul2(o01[j], s01);
            o23[j] = fmul2(o23[j], s23);
        }
        float4 v0 = *(const float4*)(vb + 0 * ROW_F + ln * 4);
        float4 v1 = *(const float4*)(vb + 1 * ROW_F + ln * 4);
        float4 v2 = *(const float4*)(vb + 2 * ROW_F + ln * 4);
        float4 v3 = *(const float4*)(vb + 3 * ROW_F + ln * 4);
#define PVROW(vv, pp)                                                    \
        do {                                                             \
            u64 q01 = f2pack(pp.x, pp.y), q23 = f2pack(pp.z, pp.w);      \
            o01[0] = ffma2(f2pack(vv.x, vv.x), q01, o01[0]);             \
            o23[0] = ffma2(f2pack(vv.x, vv.x), q23, o23[0]);             \
            o01[1] = ffma2(f2pack(vv.y, vv.y), q01, o01[1]);             \
            o23[1] = ffma2(f2pack(vv.y, vv.y), q23, o23[1]);             \
            o01[2] = ffma2(f2pack(vv.z, vv.z), q01, o01[2]);             \
            o23[2] = ffma2(f2pack(vv.z, vv.z), q23, o23[2]);             \
            o01[3] = ffma2(f2pack(vv.w, vv.w), q01, o01[3]);             \
            o23[3] = ffma2(f2pack(vv.w, vv.w), q23, o23[3]);             \
        } while (0)
        PVROW(v0, p0); PVROW(v1, p1); PVROW(v2, p2); PVROW(v3, p3);
#undef PVROW
    }
    CP_WAIT(0);

    __syncthreads();
    if (ln == 0) {
        msm[wv * 4 + 0] = m.x; msm[wv * 4 + 1] = m.y;
        msm[wv * 4 + 2] = m.z; msm[wv * 4 + 3] = m.w;
        ssm[wv * 4 + 0] = s.x; ssm[wv * 4 + 1] = s.y;
        ssm[wv * 4 + 2] = s.z; ssm[wv * 4 + 3] = s.w;
    }
    float* ov = stg;
#pragma unroll
    for (int j = 0; j < 4; j++)
        ((float4*)(ov + (wv * 32 + ln) * 16))[j] =
            make_float4(f2lo(o01[j]), f2hi(o01[j]), f2lo(o23[j]), f2hi(o23[j]));
    __syncthreads();
    if (tid < 4) {
        int g = tid;
        float M = -1e30f;
#pragma unroll
        for (int w = 0; w < 8; w++) M = fmaxf(M, msm[w * 4 + g]);
        float S = 0.f;
#pragma unroll
        for (int w = 0; w < 8; w++) {
            float e = __expf(msm[w * 4 + g] - M);
            wgt[w * 4 + g] = e;
            S += ssm[w * 4 + g] * e;
        }
        invS[g] = 1.f / S;
    }
    __syncthreads();
    if (tid < 128) {
        int dl = tid >> 2, j = tid & 3;
        int dd = dl * 4 + j;
        float o0 = 0.f, o1 = 0.f, o2 = 0.f, o3 = 0.f;
#pragma unroll
        for (int w = 0; w < 8; w++) {
            float4 pw = ((const float4*)(ov + (w * 32 + dl) * 16))[j];
            o0 += pw.x * wgt[w * 4 + 0];
            o1 += pw.y * wgt[w * 4 + 1];
            o2 += pw.z * wgt[w * 4 + 2];
            o3 += pw.w * wgt[w * 4 + 3];
        }
        float* ob = g_attn + b * 4096 + kvh * 512;
        ob[0 * 128 + dd] = o0 * invS[0];
        ob[1 * 128 + dd] = o1 * invS[1];
        ob[2 * 128 + dd] = o2 * invS[2];
        ob[3 * 128 + dd] = o3 * invS[3];
    }
}

// ---- final split-K reduction ----------------------------------------------
__global__ void reduce_out(float* __restrict__ out, int n)
{
    int i = blockIdx.x * blockDim.x + threadIdx.x;
    if (i < n) {
        float x = 0.f;
#pragma unroll
        for (int s = 0; s < S_SPLIT; s++) x += g_wo_part[(size_t)s * n + i];
        out[i] = x;
    }
}

extern "C" void kernel_launch(void* const* d_in, const int* in_sizes, int n_in,
                              void* d_out, int out_size)
{
    const float* hidden = (const float*)d_in[0];
    const float* wqkv   = (const float*)d_in[1];
    const float* wo     = (const float*)d_in[2];
    const float* kc     = (const float*)d_in[3];
    const float* vc     = (const float*)d_in[4];
    const int*   pos1d  = (const int*)d_in[5];
    const int*   blkoff = (const int*)d_in[6];
    const int*   kvlens = (const int*)d_in[7];
    float* out = (float*)d_out;

    static bool attr_done = false;
    if (!attr_done) {
        cudaFuncSetAttribute(attn_kernel, cudaFuncAttributeMaxDynamicSharedMemorySize, ATTN_SMEM);
        attr_done = true;
    }

    float *qkv_part, *wo_part, *attn_in;
    cudaGetSymbolAddress((void**)&qkv_part, g_qkv_part);
    cudaGetSymbolAddress((void**)&wo_part,  g_wo_part);
    cudaGetSymbolAddress((void**)&attn_in,  g_attn);

    gemm_split<<<dim3(12, 32), 128>>>(hidden, wqkv, qkv_part, 6144);   // #1
    qkv_reduce_rope<<<dim3(32, 4), 256>>>(pos1d);                      // #2
    noop_kernel<<<1, 32>>>();                                          // #3
    noop_kernel<<<1, 32>>>();                                          // #4
    noop_kernel<<<1, 32>>>();                                          // #5
    attn_kernel<<<256, 256, ATTN_SMEM>>>(kc, vc, blkoff, kvlens);      // #6 (ncu)
    gemm_split<<<dim3(8, 32), 128>>>(attn_in, wo, wo_part, 4096);      // #7
    reduce_out<<<512, 256>>>(out, 32 * 4096);                          // #8
}

// round 14
// speedup vs baseline: 2.0421x; 1.0093x over previous
#include <cuda_runtime.h>
#include <math.h>
#include <stdint.h>

typedef unsigned long long u64;

#define S_SPLIT 32
#define KC      128

__device__ float g_qkv_part[S_SPLIT * 32 * 6144];
__device__ float g_qkv[32 * 6144];
__device__ float g_attn[32 * 4096];
__device__ float g_wo_part[S_SPLIT * 32 * 4096];

__device__ __forceinline__ u64 f2pack(float lo, float hi) {
    u64 r; asm("mov.b64 %0,{%1,%2};" : "=l"(r) : "f"(lo), "f"(hi)); return r;
}
__device__ __forceinline__ u64 ffma2(u64 a, u64 b, u64 c) {
    u64 d; asm("fma.rn.f32x2 %0,%1,%2,%3;" : "=l"(d) : "l"(a), "l"(b), "l"(c)); return d;
}
__device__ __forceinline__ u64 fmul2(u64 a, u64 b) {
    u64 d; asm("mul.rn.f32x2 %0,%1,%2;" : "=l"(d) : "l"(a), "l"(b)); return d;
}
__device__ __forceinline__ float f2lo(u64 v) {
    float lo, hi; asm("mov.b64 {%0,%1},%2;" : "=f"(lo), "=f"(hi) : "l"(v)); return lo;
}
__device__ __forceinline__ float f2hi(u64 v) {
    float lo, hi; asm("mov.b64 {%0,%1},%2;" : "=f"(lo), "=f"(hi) : "l"(v)); return hi;
}
__device__ __forceinline__ uint32_t s2u(const void* p) {
    return (uint32_t)__cvta_generic_to_shared(p);
}
__device__ __forceinline__ void cp16(uint32_t dst, const void* src) {
    asm volatile("cp.async.cg.shared.global [%0], [%1], 16;" :: "r"(dst), "l"(src));
}
#define CP_COMMIT() asm volatile("cp.async.commit_group;")
#define CP_WAIT(n)  asm volatile("cp.async.wait_group %0;" :: "n"(n))

// ---- noop: shifts ncu capture point (2 harness pre-launches + gemm + rope
// + this noop puts attn_kernel at global launch #6 = ncu -s 5 target) ------
__global__ void noop_kernel() {}

// ---- split-K GEMM partial with cp.async W staging -------------------------
#define GNST 4
__global__ __launch_bounds__(128, 2)
void gemm_split(const float* __restrict__ A, const float* __restrict__ W,
                float* __restrict__ part, int N)
{
    __shared__ float2 as2[32][KC];          // 32768 B
    __shared__ float  wstg[GNST][1024];     // 16384 B
    const int K = 4096;
    const int k0 = blockIdx.y * KC;
    const int tid = threadIdx.x;

    for (int i = tid; i < 32 * KC; i += 128) {
        int m = i >> 7, kk = i & (KC - 1);
        float a = A[m * K + k0 + kk];
        as2[m][kk] = make_float2(a, a);
    }

    const uint32_t wbase = s2u(wstg);
    const float* Wrow = W + (size_t)k0 * N + blockIdx.x * 512 + tid * 4;
#pragma unroll
    for (int s = 0; s < GNST - 1; s++) {
        cp16(wbase + (uint32_t)((s * 1024 +   0) + tid * 4) * 4u,
             Wrow + (size_t)(2 * s) * N);
        cp16(wbase + (uint32_t)((s * 1024 + 512) + tid * 4) * 4u,
             Wrow + (size_t)(2 * s + 1) * N);
        CP_COMMIT();
    }
    __syncthreads();

    u64 acc01[32], acc23[32];
#pragma unroll
    for (int m = 0; m < 32; m++) { acc01[m] = 0ull; acc23[m] = 0ull; }

#pragma unroll 1
    for (int it = 0; it < 64; it++) {
        CP_WAIT(2);
        const float* ws = wstg[it & (GNST - 1)];
        u64 wa0 = *(const u64*)(ws + tid * 4);
        u64 wa1 = *(const u64*)(ws + tid * 4 + 2);
        u64 wb0 = *(const u64*)(ws + 512 + tid * 4);
        u64 wb1 = *(const u64*)(ws + 512 + tid * 4 + 2);
        if (it + GNST - 1 < 64) {
            int s = (it + GNST - 1) & (GNST - 1);
            cp16(wbase + (uint32_t)((s * 1024 +   0) + tid * 4) * 4u,
                 Wrow + (size_t)(2 * (it + GNST - 1)) * N);
            cp16(wbase + (uint32_t)((s * 1024 + 512) + tid * 4) * 4u,
                 Wrow + (size_t)(2 * (it + GNST - 1) + 1) * N);
            CP_COMMIT();
        } else {
            CP_COMMIT();
        }
        const int kk = 2 * it;
#pragma unroll
        for (int m = 0; m < 32; m++) {
            const u64* pa = (const u64*)&as2[m][kk];
            u64 a0 = pa[0], a1 = pa[1];
            acc01[m] = ffma2(a0, wa0, acc01[m]);
            acc23[m] = ffma2(a0, wa1, acc23[m]);
            acc01[m] = ffma2(a1, wb0, acc01[m]);
            acc23[m] = ffma2(a1, wb1, acc23[m]);
        }
    }

    float* op = part + (size_t)blockIdx.y * 32 * N + blockIdx.x * 512 + tid * 4;
#pragma unroll
    for (int m = 0; m < 32; m++) {
        *(u64*)(op + (size_t)m * N)     = acc01[m];
        *(u64*)(op + (size_t)m * N + 2) = acc23[m];
    }
}

// ---- reduce QKV partials + RoPE; grid (32 rows, 4 col-chunks) -------------
__global__ void qkv_reduce_rope(const int* __restrict__ pos1d)
{
    __shared__ float cs[64], sn[64];
    const int b = blockIdx.x;
    const int tid = threadIdx.x;

    if (tid < 64) {
        float freq = (float)pow(1.0e6, -(double)tid / 64.0);
        float ang = (float)pos1d[b] * freq;
        double sd, cd; sincos((double)ang, &sd, &cd);
        cs[tid] = (float)cd; sn[tid] = (float)sd;
    }
    __syncthreads();

    const int beg = blockIdx.y * 896, end = beg + 896;
    for (int idx = beg + tid; idx < end; idx += 256) {
        if (idx < 2560) {
            int col1, j;
            if (idx < 2048) { int h = idx >> 6; j = idx & 63; col1 = h * 128 + j; }
            else { int t = idx - 2048; int kvh = t >> 6; j = t & 63; col1 = 4096 + kvh * 128 + j; }
            int col2 = col1 + 64;
            float x1 = 0.f, x2 = 0.f;
#pragma unroll
            for (int s = 0; s < S_SPLIT; s++) {
                x1 += g_qkv_part[(s * 32 + b) * 6144 + col1];
                x2 += g_qkv_part[(s * 32 + b) * 6144 + col2];
            }
            float c = cs[j], sv = sn[j];
            g_qkv[b * 6144 + col1] = x1 * c - x2 * sv;
            g_qkv[b * 6144 + col2] = x2 * c + x1 * sv;
        } else {
            int col = 5120 + (idx - 2560);
            float x = 0.f;
#pragma unroll
            for (int s = 0; s < S_SPLIT; s++)
                x += g_qkv_part[(s * 32 + b) * 6144 + col];
            g_qkv[b * 6144 + col] = x;
        }
    }
}

// ---- flash-decode paged GQA attention, per-warp cp.async pipelines --------
#define W_STEPS  128
#define ROW_F    132
#define STG_FL   (8 * ROW_F)
#define WNSTAGE  3
#define WARP_STG (WNSTAGE * STG_FL)
#define ATTN_SMEM ((8 * WARP_STG + 512 + 104) * 4)

__global__ __launch_bounds__(256, 2)
void attn_kernel(const float* __restrict__ kc, const float* __restrict__ vc,
                 const int* __restrict__ blkoff, const int* __restrict__ kvlens)
{
    extern __shared__ float sm[];
    float* stg  = sm;
    float* qp   = sm + 8 * WARP_STG;
    float* msm  = qp + 512;
    float* ssm  = msm + 32;
    float* wgt  = ssm + 32;
    float* invS = wgt + 32;
    __shared__ int pblk[64];

    const int b = blockIdx.x >> 3, kvh = blockIdx.x & 7;
    const int tid = threadIdx.x;
    const int Lv = kvlens[b];
    const int posn = Lv - 1;
    const float* qkv_b = g_qkv + b * 6144;

    for (int i = tid; i < 512; i += 256) {
        int g = i >> 7, d = i & 127;
        qp[i] = qkv_b[(kvh * 4 + g) * 128 + d] * 0.08838834764831845f;
    }
    if (tid < 64) pblk[tid] = blkoff[b * 64 + tid];
    __syncthreads();

    const int wv = tid >> 5, ln = tid & 31;
    const int lane16 = ln & 15, half = ln >> 4;
    const int rbase = wv * 512;
    float* wstg = stg + wv * WARP_STG;
    const uint32_t wstg_u32 = s2u(wstg);
    const float* kfresh = qkv_b + 4096 + kvh * 128;
    const float* vfresh = qkv_b + 5120 + kvh * 128;

    float4 qA[4], qB[4];
#pragma unroll
    for (int g = 0; g < 4; g++) {
        qA[g] = *(const float4*)&qp[g * 128 + lane16 * 4];
        qB[g] = *(const float4*)&qp[g * 128 + 64 + lane16 * 4];
    }

#define LOAD_STEP(st, slot)                                                     \
    do {                                                                        \
        uint32_t sb = wstg_u32 + (uint32_t)((slot) * STG_FL) * 4u;              \
        _Pragma("unroll")                                                       \
        for (int j = 0; j < 8; j++) {                                           \
            int l = rbase + (st) * 4 + (j & 3);                                 \
            const float* cache = (j < 4) ? kc : vc;                             \
            const float* fr    = (j < 4) ? kfresh : vfresh;                     \
            const float* src;                                                   \
            if (l == posn) src = fr + ln * 4;                                   \
            else {                                                              \
                int phys = pblk[l >> 6];                                        \
                src = cache + (((size_t)phys * 64 + (l & 63)) * 8 + kvh) * 128  \
                      + ln * 4;                                                 \
            }                                                                   \
            cp16(sb + (uint32_t)(j * ROW_F + ln * 4) * 4u, src);                \
        }                                                                       \
        CP_COMMIT();                                                            \
    } while (0)

    LOAD_STEP(0, 0);
    LOAD_STEP(1, 1);

    float4 m = make_float4(-1e30f, -1e30f, -1e30f, -1e30f);
    float4 s = make_float4(0.f, 0.f, 0.f, 0.f);
    u64 o01[4], o23[4];
#pragma unroll
    for (int j = 0; j < 4; j++) { o01[j] = 0ull; o23[j] = 0ull; }

#pragma unroll 1
    for (int t = 0; t < W_STEPS; t++) {
        __syncwarp();
        if (t + 2 < W_STEPS) LOAD_STEP(t + 2, (t + 2) % WNSTAGE);
        else CP_COMMIT();
        CP_WAIT(2);
        __syncwarp();
        const float* kb = wstg + (t % WNSTAGE) * STG_FL;
        const float* vb = kb + 4 * ROW_F;

        float4 sA, sB;
#pragma unroll
        for (int pass = 0; pass < 2; pass++) {
            int r = pass * 2 + half;
            const float* kr = kb + r * ROW_F;
            float4 kA = *(const float4*)(kr + lane16 * 4);
            float4 kB = *(const float4*)(kr + 64 + lane16 * 4);
            float a0, a1, a2, a3;
#define DOT8(g) (kA.x*qA[g].x + kA.y*qA[g].y + kA.z*qA[g].z + kA.w*qA[g].w + \
                 kB.x*qB[g].x + kB.y*qB[g].y + kB.z*qB[g].z + kB.w*qB[g].w)
            a0 = DOT8(0); a1 = DOT8(1); a2 = DOT8(2); a3 = DOT8(3);
#undef DOT8
#pragma unroll
            for (int o = 8; o > 0; o >>= 1) {
                a0 += __shfl_xor_sync(0xffffffffu, a0, o);
                a1 += __shfl_xor_sync(0xffffffffu, a1, o);
                a2 += __shfl_xor_sync(0xffffffffu, a2, o);
                a3 += __shfl_xor_sync(0xffffffffu, a3, o);
            }
            if (rbase + t * 4 + r >= Lv) { a0 = a1 = a2 = a3 = -1e30f; }
            if (pass == 0) sA = make_float4(a0, a1, a2, a3);
            else           sB = make_float4(a0, a1, a2, a3);
        }
        float4 tA, tB;
        tA.x = __shfl_xor_sync(0xffffffffu, sA.x, 16);
        tA.y = __shfl_xor_sync(0xffffffffu, sA.y, 16);
        tA.z = __shfl_xor_sync(0xffffffffu, sA.z, 16);
        tA.w = __shfl_xor_sync(0xffffffffu, sA.w, 16);
        tB.x = __shfl_xor_sync(0xffffffffu, sB.x, 16);
        tB.y = __shfl_xor_sync(0xffffffffu, sB.y, 16);
        tB.z = __shfl_xor_sync(0xffffffffu, sB.z, 16);
        tB.w = __shfl_xor_sync(0xffffffffu, sB.w, 16);
        float4 r0 = half ? tA : sA;
        float4 r1 = half ? sA : tA;
        float4 r2 = half ? tB : sB;
        float4 r3 = half ? sB : tB;

        float4 mn;
        mn.x = fmaxf(fmaxf(fmaxf(r0.x, r1.x), fmaxf(r2.x, r3.x)), m.x);
        mn.y = fmaxf(fmaxf(fmaxf(r0.y, r1.y), fmaxf(r2.y, r3.y)), m.y);
        mn.z = fmaxf(fmaxf(fmaxf(r0.z, r1.z), fmaxf(r2.z, r3.z)), m.z);
        mn.w = fmaxf(fmaxf(fmaxf(r0.w, r1.w), fmaxf(r2.w, r3.w)), m.w);
        float4 sc4;
        sc4.x = __expf(m.x - mn.x); sc4.y = __expf(m.y - mn.y);
        sc4.z = __expf(m.z - mn.z); sc4.w = __expf(m.w - mn.w);
        float4 p0, p1, p2, p3;
        p0.x = __expf(r0.x - mn.x); p0.y = __expf(r0.y - mn.y);
        p0.z = __expf(r0.z - mn.z); p0.w = __expf(r0.w - mn.w);
        p1.x = __expf(r1.x - mn.x); p1.y = __expf(r1.y - mn.y);
        p1.z = __expf(r1.z - mn.z); p1.w = __expf(r1.w - mn.w);
        p2.x = __expf(r2.x - mn.x); p2.y = __expf(r2.y - mn.y);
        p2.z = __expf(r2.z - mn.z); p2.w = __expf(r2.w - mn.w);
        p3.x = __expf(r3.x - mn.x); p3.y = __expf(r3.y - mn.y);
        p3.z = __expf(r3.z - mn.z); p3.w = __expf(r3.w - mn.w);
        s.x = s.x * sc4.x + p0.x + p1.x + p2.x + p3.x;
        s.y = s.y * sc4.y + p0.y + p1.y + p2.y + p3.y;
        s.z = s.z * sc4.z + p0.z + p1.z + p2.z + p3.z;
        s.w = s.w * sc4.w + p0.w + p1.w + p2.w + p3.w;
        m = mn;

        u64 s01 = f2pack(sc4.x, sc4.y), s23 = f2pack(sc4.z, sc4.w);
#pragma unroll
        for (int j = 0; j < 4; j++) {
            o01[j] = fmul2(o01[j], s01);
            o23[j] = fmul2(o23[j], s23);
        }
        float4 v0 = *(const float4*)(vb + 0 * ROW_F + ln * 4);
        float4 v1 = *(const float4*)(vb + 1 * ROW_F + ln * 4);
        float4 v2 = *(const float4*)(vb + 2 * ROW_F + ln * 4);
        float4 v3 = *(const float4*)(vb + 3 * ROW_F + ln * 4);
#define PVROW(vv, pp)                                                    \
        do {                                                             \
            u64 q01 = f2pack(pp.x, pp.y), q23 = f2pack(pp.z, pp.w);      \
            o01[0] = ffma2(f2pack(vv.x, vv.x), q01, o01[0]);             \
            o23[0] = ffma2(f2pack(vv.x, vv.x), q23, o23[0]);             \
            o01[1] = ffma2(f2pack(vv.y, vv.y), q01, o01[1]);             \
            o23[1] = ffma2(f2pack(vv.y, vv.y), q23, o23[1]);             \
            o01[2] = ffma2(f2pack(vv.z, vv.z), q01, o01[2]);             \
            o23[2] = ffma2(f2pack(vv.z, vv.z), q23, o23[2]);             \
            o01[3] = ffma2(f2pack(vv.w, vv.w), q01, o01[3]);             \
            o23[3] = ffma2(f2pack(vv.w, vv.w), q23, o23[3]);             \
        } while (0)
        PVROW(v0, p0); PVROW(v1, p1); PVROW(v2, p2); PVROW(v3, p3);
#undef PVROW
    }
    CP_WAIT(0);

    __syncthreads();
    if (ln == 0) {
        msm[wv * 4 + 0] = m.x; msm[wv * 4 + 1] = m.y;
        msm[wv * 4 + 2] = m.z; msm[wv * 4 + 3] = m.w;
        ssm[wv * 4 + 0] = s.x; ssm[wv * 4 + 1] = s.y;
        ssm[wv * 4 + 2] = s.z; ssm[wv * 4 + 3] = s.w;
    }
    float* ov = stg;
#pragma unroll
    for (int j = 0; j < 4; j++)
        ((float4*)(ov + (wv * 32 + ln) * 16))[j] =
            make_float4(f2lo(o01[j]), f2hi(o01[j]), f2lo(o23[j]), f2hi(o23[j]));
    __syncthreads();
    if (tid < 4) {
        int g = tid;
        float M = -1e30f;
#pragma unroll
        for (int w = 0; w < 8; w++) M = fmaxf(M, msm[w * 4 + g]);
        float S = 0.f;
#pragma unroll
        for (int w = 0; w < 8; w++) {
            float e = __expf(msm[w * 4 + g] - M);
            wgt[w * 4 + g] = e;
            S += ssm[w * 4 + g] * e;
        }
        invS[g] = 1.f / S;
    }
    __syncthreads();
    if (tid < 128) {
        int dl = tid >> 2, j = tid & 3;
        int dd = dl * 4 + j;
        float o0 = 0.f, o1 = 0.f, o2 = 0.f, o3 = 0.f;
#pragma unroll
        for (int w = 0; w < 8; w++) {
            float4 pw = ((const float4*)(ov + (w * 32 + dl) * 16))[j];
            o0 += pw.x * wgt[w * 4 + 0];
            o1 += pw.y * wgt[w * 4 + 1];
            o2 += pw.z * wgt[w * 4 + 2];
            o3 += pw.w * wgt[w * 4 + 3];
        }
        float* ob = g_attn + b * 4096 + kvh * 512;
        ob[0 * 128 + dd] = o0 * invS[0];
        ob[1 * 128 + dd] = o1 * invS[1];
        ob[2 * 128 + dd] = o2 * invS[2];
        ob[3 * 128 + dd] = o3 * invS[3];
    }
}

// ---- final split-K reduction ----------------------------------------------
__global__ void reduce_out(float* __restrict__ out, int n)
{
    int i = blockIdx.x * blockDim.x + threadIdx.x;
    if (i < n) {
        float x = 0.f;
#pragma unroll
        for (int s = 0; s < S_SPLIT; s++) x += g_wo_part[(size_t)s * n + i];
        out[i] = x;
    }
}

extern "C" void kernel_launch(void* const* d_in, const int* in_sizes, int n_in,
                              void* d_out, int out_size)
{
    const float* hidden = (const float*)d_in[0];
    const float* wqkv   = (const float*)d_in[1];
    const float* wo     = (const float*)d_in[2];
    const float* kc     = (const float*)d_in[3];
    const float* vc     = (const float*)d_in[4];
    const int*   pos1d  = (const int*)d_in[5];
    const int*   blkoff = (const int*)d_in[6];
    const int*   kvlens = (const int*)d_in[7];
    float* out = (float*)d_out;

    static bool attr_done = false;
    if (!attr_done) {
        cudaFuncSetAttribute(attn_kernel, cudaFuncAttributeMaxDynamicSharedMemorySize, ATTN_SMEM);
        attr_done = true;
    }

    float *qkv_part, *wo_part, *attn_in;
    cudaGetSymbolAddress((void**)&qkv_part, g_qkv_part);
    cudaGetSymbolAddress((void**)&wo_part,  g_wo_part);
    cudaGetSymbolAddress((void**)&attn_in,  g_attn);

    // 2 harness pre-launches + these: attn_kernel lands at global #6 (ncu -s 5)
    gemm_split<<<dim3(12, 32), 128>>>(hidden, wqkv, qkv_part, 6144);
    qkv_reduce_rope<<<dim3(32, 4), 256>>>(pos1d);
    noop_kernel<<<1, 32>>>();
    attn_kernel<<<256, 256, ATTN_SMEM>>>(kc, vc, blkoff, kvlens);
    gemm_split<<<dim3(8, 32), 128>>>(attn_in, wo, wo_part, 4096);
    reduce_out<<<512, 256>>>(out, 32 * 4096);
}